// round 13
// baseline (speedup 1.0000x reference)
#include <cuda_runtime.h>
#include <cuda_bf16.h>
#include <cstdint>

#define NG 512   // total groups
#define TG 32    // tokens per group
#define DD 1024  // model dim
#define NE 32    // experts
#define NS 128   // expert hidden size

__device__ float g_w[NG * NE];
__device__ int   g_sel[NG * NE];
__device__ float g_Lp[2 * NG * TG * NE];   // split-K partial logits
__device__ __nv_bfloat16 g_B1hi[(size_t)NE * NS * DD];
__device__ __nv_bfloat16 g_B1lo[(size_t)NE * NS * DD];
__device__ __nv_bfloat16 g_B2hi[(size_t)NE * DD * NS];
__device__ __nv_bfloat16 g_B2lo[(size_t)NE * DD * NS];
__device__ __nv_bfloat16 g_Ihi[(size_t)NE * NG * NS];
__device__ __nv_bfloat16 g_Ilo[(size_t)NE * NG * NS];

// ============================ helpers ============================
static __device__ __forceinline__ uint32_t smem_to_u32(const void* p) {
    uint32_t a;
    asm("{ .reg .u64 t; cvta.to.shared.u64 t, %1; cvt.u32.u64 %0, t; }"
        : "=r"(a) : "l"(p));
    return a;
}
static __device__ __forceinline__ void ldmat_x4(
    uint32_t& r0, uint32_t& r1, uint32_t& r2, uint32_t& r3, uint32_t addr)
{
    asm volatile("ldmatrix.sync.aligned.m8n8.x4.shared.b16 {%0,%1,%2,%3}, [%4];"
                 : "=r"(r0), "=r"(r1), "=r"(r2), "=r"(r3) : "r"(addr));
}
static __device__ __forceinline__ void mma16816(
    float* d, uint32_t a0, uint32_t a1, uint32_t a2, uint32_t a3,
    uint32_t b0, uint32_t b1)
{
    asm volatile("mma.sync.aligned.m16n8k16.row.col.f32.bf16.bf16.f32 "
                 "{%0,%1,%2,%3}, {%4,%5,%6,%7}, {%8,%9}, {%0,%1,%2,%3};"
                 : "+f"(d[0]), "+f"(d[1]), "+f"(d[2]), "+f"(d[3])
                 : "r"(a0), "r"(a1), "r"(a2), "r"(a3), "r"(b0), "r"(b1));
}
#define CP_ASYNC16(sm, gp) \
    asm volatile("cp.async.cg.shared.global [%0], [%1], 16;" :: "r"(sm), "l"(gp))
#define CP_COMMIT() asm volatile("cp.async.commit_group;" ::: "memory")
#define CP_WAIT0()  asm volatile("cp.async.wait_group 0;" ::: "memory")

static __device__ __forceinline__ unsigned long long pack2(float lo, float hi) {
    unsigned long long r;
    asm("mov.b64 %0, {%1, %2};" : "=l"(r) : "f"(lo), "f"(hi));
    return r;
}
static __device__ __forceinline__ void fma2(unsigned long long &d,
                                            unsigned long long a, unsigned long long b) {
    asm("fma.rn.f32x2 %0, %1, %2, %0;" : "+l"(d) : "l"(a), "l"(b));
}
static __device__ __forceinline__ float2 unpack2(unsigned long long v) {
    float lo, hi;
    asm("mov.b64 {%0, %1}, %2;" : "=f"(lo), "=f"(hi) : "l"(v));
    return make_float2(lo, hi);
}
static __device__ __forceinline__ void split_bf16(float v, __nv_bfloat16& h, __nv_bfloat16& l) {
    h = __float2bfloat16_rn(v);
    l = __float2bfloat16_rn(v - __bfloat162float(h));
}
static __device__ __forceinline__ uint32_t packbf(__nv_bfloat16 a, __nv_bfloat16 b) {
    __nv_bfloat162 p = __halves2bfloat162(a, b);
    return *(uint32_t*)&p;
}

// ---------------------------------------------------------------------------
// Prologue: blocks [0,512): router split-K partials; blocks [512, 4608):
// f1 weight transpose + bf16 split (B2 prep moved into ff1's grid).
// ---------------------------------------------------------------------------
#define RT 64
#define RDC 64
#define XPAD 68
#define NB_ROUTER 512

__global__ __launch_bounds__(256) void prologue_kernel(
    const float* __restrict__ x, const float* __restrict__ ctrl,
    const float* __restrict__ f1)
{
    __shared__ __align__(16) float sm[RT * XPAD + RDC * NE];
    int b   = blockIdx.x;
    int tid = threadIdx.x;

    if (b < NB_ROUTER) {
        // ----- router partial -----
        float* xs = sm;                       // [64][XPAD]
        float (*cs)[NE] = (float(*)[NE])(sm + RT * XPAD);
        int tokbase = (b & 255) * RT;
        int khalf   = b >> 8;
        int kbase   = khalf * (DD / 2);

        int mt = (tid >> 3) << 1;   // token pair 0..62
        int et = (tid & 7) << 2;    // expert 0..28

        unsigned long long acc[2][2];
        acc[0][0] = 0ULL; acc[0][1] = 0ULL; acc[1][0] = 0ULL; acc[1][1] = 0ULL;

        for (int dc = kbase; dc < kbase + DD / 2; dc += RDC) {
            __syncthreads();
#pragma unroll
            for (int it = 0; it < 4; it++) {
                int q  = tid + (it << 8);
                int t  = q >> 4;
                int d4 = (q & 15) << 2;
                *(float4*)&xs[t * XPAD + d4] =
                    *(const float4*)(x + (size_t)(tokbase + t) * DD + dc + d4);
            }
#pragma unroll
            for (int it = 0; it < 2; it++) {
                int q  = tid + (it << 8);
                int d  = q >> 3;
                int e4 = (q & 7) << 2;
                *(float4*)&cs[d][e4] = *(const float4*)(ctrl + (size_t)(dc + d) * NE + e4);
            }
            __syncthreads();
#pragma unroll 4
            for (int d = 0; d < RDC; d += 4) {
                float4 xr0 = *(const float4*)&xs[(mt    ) * XPAD + d];
                float4 xr1 = *(const float4*)&xs[(mt + 1) * XPAD + d];
#pragma unroll
                for (int dd = 0; dd < 4; dd++) {
                    ulonglong2 cb = *(const ulonglong2*)&cs[d + dd][et];
                    float v0 = (dd == 0) ? xr0.x : (dd == 1) ? xr0.y : (dd == 2) ? xr0.z : xr0.w;
                    float v1 = (dd == 0) ? xr1.x : (dd == 1) ? xr1.y : (dd == 2) ? xr1.z : xr1.w;
                    unsigned long long a0 = pack2(v0, v0);
                    unsigned long long a1 = pack2(v1, v1);
                    fma2(acc[0][0], a0, cb.x);
                    fma2(acc[0][1], a0, cb.y);
                    fma2(acc[1][0], a1, cb.x);
                    fma2(acc[1][1], a1, cb.y);
                }
            }
        }

        float* Lp = g_Lp + (size_t)khalf * (NG * TG * NE);
#pragma unroll
        for (int i = 0; i < 2; i++) {
            float2 v0 = unpack2(acc[i][0]);
            float2 v1 = unpack2(acc[i][1]);
            *(float4*)&Lp[(size_t)(tokbase + mt + i) * NE + et] =
                make_float4(v0.x, v0.y, v1.x, v1.y);
        }
    } else {
        // ----- f1 transpose + bf16 split -----
        int idx = b - NB_ROUTER;                  // 0..4095
        float (*tile)[33] = (float(*)[33])sm;
        int e  = idx >> 7;           // 0..31
        int kt = idx & 31;
        int nt = (idx >> 5) & 3;
        int tx = tid & 31, ty = tid >> 5;  // 32 x 8
#pragma unroll
        for (int r = 0; r < 4; r++) {
            int k = kt * 32 + ty + r * 8;
            tile[ty + r * 8][tx] = f1[((size_t)k * NE + e) * NS + nt * 32 + tx];
        }
        __syncthreads();
#pragma unroll
        for (int r = 0; r < 4; r++) {
            int n = nt * 32 + ty + r * 8;
            int k = kt * 32 + tx;
            float v = tile[tx][ty + r * 8];
            __nv_bfloat16 h, l;
            split_bf16(v, h, l);
            size_t ix = ((size_t)e * NS + n) * DD + k;
            g_B1hi[ix] = h;
            g_B1lo[ix] = l;
        }
    }
}

__global__ __launch_bounds__(32) void router_fin_kernel()
{
    int g = blockIdx.x;
    int e = threadIdx.x;
    const float* p0 = g_Lp + (size_t)(g * TG) * NE + e;
    const float* p1 = p0 + (size_t)NG * TG * NE;
    const float step = 1e-6f / 31.0f;

    float L[TG];
    float m = -1e30f;
    int am = 0;
#pragma unroll
    for (int t = 0; t < TG; t++) {
        float v = p0[t * NE] + p1[t * NE] + (float)t * step;
        L[t] = v;
        if (v > m) { m = v; am = t; }
    }
    float s = 0.f;
#pragma unroll
    for (int t = 0; t < TG; t++) s += __expf(L[t] - m);
    g_w[g * NE + e]   = 1.0f / s;
    g_sel[g * NE + e] = am;
}

// ---------------------------------------------------------------------------
// FF1 fused kernel:
//   blocks [0,256): GEMM  D[64g,128s] = (w*x[sel]) @ B1^T (3-term bf16 split)
//   blocks [256, 4352): f2 transpose/split + out zero-fill (uses idle SMs)
// ---------------------------------------------------------------------------
#define RS 80
#define F1_AH 0
#define F1_AL 5120
#define F1_BH 10240
#define F1_BL 20480
#define F1_BUF 30720
#define F1_SMEM (2 * F1_BUF)
#define NB_FF1 256

__global__ __launch_bounds__(256, 3) void ff1_mma_kernel(
    const float* __restrict__ x, const float* __restrict__ f1b,
    const float* __restrict__ f2, float* __restrict__ out, int out_n4)
{
    extern __shared__ __align__(16) char smc[];
    int tid = threadIdx.x;
    int b   = blockIdx.x;

    if (b >= NB_FF1) {
        // ================= B2 prep + zero-fill =================
        int idx = b - NB_FF1;                     // 0..4095
        // zero-fill: 1024 float4 per block
        {
            float4 z = make_float4(0.f, 0.f, 0.f, 0.f);
            int base = idx * 1024 + tid;
#pragma unroll
            for (int j = 0; j < 4; j++) {
                int i = base + j * 256;
                if (i < out_n4) ((float4*)out)[i] = z;
            }
        }
        float (*tile)[33] = (float(*)[33])smc;
        int e  = idx >> 7;           // 0..31
        int dt = idx & 31;
        int st = (idx >> 5) & 3;
        int tx = tid & 31, ty = tid >> 5;
#pragma unroll
        for (int r = 0; r < 4; r++) {
            int s = st * 32 + ty + r * 8;
            tile[ty + r * 8][tx] = f2[((size_t)e * NS + s) * DD + dt * 32 + tx];
        }
        __syncthreads();
#pragma unroll
        for (int r = 0; r < 4; r++) {
            int d = dt * 32 + ty + r * 8;
            int s = st * 32 + tx;
            float v = tile[tx][ty + r * 8];
            __nv_bfloat16 h, l;
            split_bf16(v, h, l);
            size_t ix = ((size_t)e * DD + d) * NS + s;
            g_B2hi[ix] = h;
            g_B2lo[ix] = l;
        }
        return;
    }

    // ================= GEMM =================
    uint32_t smu = smem_to_u32(smc);
    int lane = tid & 31;
    int wid  = tid >> 5;
    int wm   = wid >> 2;     // 0..1
    int wn   = wid & 3;      // 0..3
    int e     = b >> 3;      // 0..31
    int gbase = (b & 7) * 64;

    int ar  = tid >> 2;
    int ac0 = (tid & 3) << 1;
    int gg  = gbase + ar;
    float wv = g_w[gg * NE + e];
    const float* arow = x + (size_t)(gg * TG + g_sel[gg * NE + e]) * DD;

    int br  = tid >> 1;
    int bh2 = tid & 1;
    const __nv_bfloat16* bhrow = g_B1hi + ((size_t)e * NS + br) * DD + bh2 * 16;
    const __nv_bfloat16* blrow = g_B1lo + ((size_t)e * NS + br) * DD + bh2 * 16;
    uint32_t bdst = smu + F1_BH + br * RS + bh2 * 32;

    float acc[2][4][4];
#pragma unroll
    for (int i = 0; i < 2; i++)
#pragma unroll
        for (int j = 0; j < 4; j++)
#pragma unroll
            for (int q = 0; q < 4; q++) acc[i][j][q] = 0.f;

    float4 pa[2];

#define FF1_FETCH_A(kt) do {                                                 \
        pa[0] = *(const float4*)(arow + (kt) + ac0 * 4);                     \
        pa[1] = *(const float4*)(arow + (kt) + ac0 * 4 + 4);                 \
    } while (0)

#define FF1_STORE_A(b_) do {                                                 \
        char* bb = smc + (b_) * F1_BUF;                                      \
        _Pragma("unroll")                                                    \
        for (int j = 0; j < 2; j++) {                                        \
            float4 v = pa[j];                                                \
            v.x *= wv; v.y *= wv; v.z *= wv; v.w *= wv;                      \
            __nv_bfloat16 h0,l0,h1,l1,h2,l2,h3,l3;                           \
            split_bf16(v.x,h0,l0); split_bf16(v.y,h1,l1);                    \
            split_bf16(v.z,h2,l2); split_bf16(v.w,h3,l3);                    \
            int off = ar * RS + (ac0 + j) * 8;                               \
            *(uint2*)(bb + F1_AH + off) = make_uint2(packbf(h0,h1), packbf(h2,h3)); \
            *(uint2*)(bb + F1_AL + off) = make_uint2(packbf(l0,l1), packbf(l2,l3)); \
        }                                                                    \
    } while (0)

#define FF1_CPASYNC_B(b_, kt) do {                                           \
        uint32_t d_ = bdst + (b_) * F1_BUF;                                  \
        CP_ASYNC16(d_,                      bhrow + (kt));                   \
        CP_ASYNC16(d_ + 16,                 bhrow + (kt) + 8);               \
        CP_ASYNC16(d_ + (F1_BL - F1_BH),      blrow + (kt));                 \
        CP_ASYNC16(d_ + (F1_BL - F1_BH) + 16, blrow + (kt) + 8);             \
    } while (0)

    FF1_FETCH_A(0);
    FF1_STORE_A(0);
    FF1_CPASYNC_B(0, 0);
    CP_COMMIT();

    int cur = 0;
    for (int it = 0; it < 32; it++) {
        bool more = (it + 1 < 32);
        CP_WAIT0();
        __syncthreads();
        if (more) {
            FF1_CPASYNC_B(cur ^ 1, (it + 1) * 32);
            CP_COMMIT();
            FF1_FETCH_A((it + 1) * 32);
        }
        uint32_t bufb = smu + cur * F1_BUF;
#pragma unroll
        for (int ksb = 0; ksb < 64; ksb += 32) {
            uint32_t bh_[4][2], bl_[4][2];
#pragma unroll
            for (int nb = 0; nb < 2; nb++) {
                uint32_t baddr = bufb + F1_BH +
                    (uint32_t)((wn * 32 + nb * 16 + (lane & 7) + ((lane >> 4) & 1) * 8) * RS +
                               ((lane >> 3) & 1) * 16 + ksb);
                ldmat_x4(bh_[2*nb][0], bh_[2*nb][1], bh_[2*nb+1][0], bh_[2*nb+1][1], baddr);
                ldmat_x4(bl_[2*nb][0], bl_[2*nb][1], bl_[2*nb+1][0], bl_[2*nb+1][1],
                         baddr + (F1_BL - F1_BH));
            }
#pragma unroll
            for (int mf = 0; mf < 2; mf++) {
                uint32_t aaddr = bufb + F1_AH +
                    (uint32_t)((wm * 32 + mf * 16 + (lane & 15)) * RS +
                               (lane >> 4) * 16 + ksb);
                uint32_t ah0, ah1, ah2, ah3, al0, al1, al2, al3;
                ldmat_x4(ah0, ah1, ah2, ah3, aaddr);
                ldmat_x4(al0, al1, al2, al3, aaddr + (F1_AL - F1_AH));
#pragma unroll
                for (int nf = 0; nf < 4; nf++)
                    mma16816(acc[mf][nf], ah0, ah1, ah2, ah3, bh_[nf][0], bh_[nf][1]);
#pragma unroll
                for (int nf = 0; nf < 4; nf++)
                    mma16816(acc[mf][nf], ah0, ah1, ah2, ah3, bl_[nf][0], bl_[nf][1]);
#pragma unroll
                for (int nf = 0; nf < 4; nf++)
                    mma16816(acc[mf][nf], al0, al1, al2, al3, bh_[nf][0], bh_[nf][1]);
            }
        }
        if (more) FF1_STORE_A(cur ^ 1);
        cur ^= 1;
    }

    const float* bias = f1b + e * NS;
#pragma unroll
    for (int mf = 0; mf < 2; mf++) {
#pragma unroll
        for (int nf = 0; nf < 4; nf++) {
            int c  = wn * 32 + nf * 8 + (lane & 3) * 2;
            float b0 = bias[c], b1 = bias[c + 1];
#pragma unroll
            for (int h = 0; h < 2; h++) {
                int r = wm * 32 + mf * 16 + (lane >> 2) + h * 8;
                float v0 = fmaxf(acc[mf][nf][2*h]     + b0, 0.f);
                float v1 = fmaxf(acc[mf][nf][2*h + 1] + b1, 0.f);
                __nv_bfloat16 h0, l0, h1, l1;
                split_bf16(v0, h0, l0); split_bf16(v1, h1, l1);
                size_t ob = ((size_t)e * NG + gbase + r) * NS + c;
                *(uint32_t*)&g_Ihi[ob] = packbf(h0, h1);
                *(uint32_t*)&g_Ilo[ob] = packbf(l0, l1);
            }
        }
    }
}

// ---------------------------------------------------------------------------
// FF2: D[128g,128d] = I[128,128s] x B2^T (3-term), scatter via red.v2.
// 256 threads, warp grid 2x4, warp tile 64x32, BK=32, double-buffered.
// ---------------------------------------------------------------------------
#define F2_AH 0
#define F2_AL 10240
#define F2_BH 20480
#define F2_BL 30720
#define F2_BUF 40960
#define F2_WV  (2 * F2_BUF)
#define F2_TOK (F2_WV + 512)
#define F2_SMEM (F2_TOK + 512)

__global__ __launch_bounds__(256) void ff2_mma_kernel(float* __restrict__ out)
{
    extern __shared__ __align__(16) char smc[];
    uint32_t smu = smem_to_u32(smc);
    int tid  = threadIdx.x;
    int lane = tid & 31;
    int wid  = tid >> 5;
    int wm   = wid >> 2;
    int wn   = wid & 3;
    int e     = blockIdx.z;
    int gbase = blockIdx.x * 128;
    int nbase = blockIdx.y * 128;

    float* swv = (float*)(smc + F2_WV);
    int*   stok = (int*)(smc + F2_TOK);
    if (tid < 128) {
        int g = gbase + tid;
        swv[tid]  = g_w[g * NE + e];
        stok[tid] = g * TG + g_sel[g * NE + e];
    }

    int r_  = tid >> 1;
    int h2  = tid & 1;
    const __nv_bfloat16* ahrow = g_Ihi + ((size_t)e * NG + gbase + r_) * NS + h2 * 16;
    const __nv_bfloat16* alrow = g_Ilo + ((size_t)e * NG + gbase + r_) * NS + h2 * 16;
    const __nv_bfloat16* bhrow = g_B2hi + ((size_t)e * DD + nbase + r_) * NS + h2 * 16;
    const __nv_bfloat16* blrow = g_B2lo + ((size_t)e * DD + nbase + r_) * NS + h2 * 16;
    uint32_t adst = smu + F2_AH + r_ * RS + h2 * 32;
    uint32_t bdst = smu + F2_BH + r_ * RS + h2 * 32;

    float acc[4][4][4];
#pragma unroll
    for (int i = 0; i < 4; i++)
#pragma unroll
        for (int j = 0; j < 4; j++)
#pragma unroll
            for (int q = 0; q < 4; q++) acc[i][j][q] = 0.f;

#define FF2_CPASYNC(b_, kt) do {                                             \
        uint32_t ad_ = adst + (b_) * F2_BUF;                                 \
        uint32_t bd_ = bdst + (b_) * F2_BUF;                                 \
        CP_ASYNC16(ad_,                       ahrow + (kt));                 \
        CP_ASYNC16(ad_ + 16,                  ahrow + (kt) + 8);             \
        CP_ASYNC16(ad_ + (F2_AL - F2_AH),      alrow + (kt));                \
        CP_ASYNC16(ad_ + (F2_AL - F2_AH) + 16, alrow + (kt) + 8);            \
        CP_ASYNC16(bd_,                       bhrow + (kt));                 \
        CP_ASYNC16(bd_ + 16,                  bhrow + (kt) + 8);             \
        CP_ASYNC16(bd_ + (F2_BL - F2_BH),      blrow + (kt));                \
        CP_ASYNC16(bd_ + (F2_BL - F2_BH) + 16, blrow + (kt) + 8);            \
    } while (0)

    FF2_CPASYNC(0, 0);
    CP_COMMIT();

    int cur = 0;
    for (int it = 0; it < 4; it++) {
        bool more = (it + 1 < 4);
        CP_WAIT0();
        __syncthreads();
        if (more) {
            FF2_CPASYNC(cur ^ 1, (it + 1) * 32);
            CP_COMMIT();
        }
        uint32_t bufb = smu + cur * F2_BUF;
#pragma unroll
        for (int ksb = 0; ksb < 64; ksb += 32) {
            uint32_t bh_[4][2], bl_[4][2];
#pragma unroll
            for (int nb = 0; nb < 2; nb++) {
                uint32_t baddr = bufb + F2_BH +
                    (uint32_t)((wn * 32 + nb * 16 + (lane & 7) + ((lane >> 4) & 1) * 8) * RS +
                               ((lane >> 3) & 1) * 16 + ksb);
                ldmat_x4(bh_[2*nb][0], bh_[2*nb][1], bh_[2*nb+1][0], bh_[2*nb+1][1], baddr);
                ldmat_x4(bl_[2*nb][0], bl_[2*nb][1], bl_[2*nb+1][0], bl_[2*nb+1][1],
                         baddr + (F2_BL - F2_BH));
            }
#pragma unroll
            for (int mf = 0; mf < 4; mf++) {
                uint32_t aaddr = bufb + F2_AH +
                    (uint32_t)((wm * 64 + mf * 16 + (lane & 15)) * RS +
                               (lane >> 4) * 16 + ksb);
                uint32_t ah0, ah1, ah2, ah3, al0, al1, al2, al3;
                ldmat_x4(ah0, ah1, ah2, ah3, aaddr);
                ldmat_x4(al0, al1, al2, al3, aaddr + (F2_AL - F2_AH));
#pragma unroll
                for (int nf = 0; nf < 4; nf++)
                    mma16816(acc[mf][nf], ah0, ah1, ah2, ah3, bh_[nf][0], bh_[nf][1]);
#pragma unroll
                for (int nf = 0; nf < 4; nf++)
                    mma16816(acc[mf][nf], ah0, ah1, ah2, ah3, bl_[nf][0], bl_[nf][1]);
#pragma unroll
                for (int nf = 0; nf < 4; nf++)
                    mma16816(acc[mf][nf], al0, al1, al2, al3, bh_[nf][0], bh_[nf][1]);
            }
        }
        cur ^= 1;
    }

#pragma unroll
    for (int mf = 0; mf < 4; mf++) {
#pragma unroll
        for (int nf = 0; nf < 4; nf++) {
            int c = wn * 32 + nf * 8 + (lane & 3) * 2;
#pragma unroll
            for (int h = 0; h < 2; h++) {
                int r = wm * 64 + mf * 16 + (lane >> 2) + h * 8;
                float wv = swv[r];
                float* p = out + (size_t)stok[r] * DD + nbase + c;
                float v0 = wv * acc[mf][nf][2*h];
                float v1 = wv * acc[mf][nf][2*h + 1];
                asm volatile("red.global.add.v2.f32 [%0], {%1, %2};"
                             :: "l"(p), "f"(v0), "f"(v1) : "memory");
            }
        }
    }
}

// ---------------------------------------------------------------------------
extern "C" void kernel_launch(void* const* d_in, const int* in_sizes, int n_in,
                              void* d_out, int out_size) {
    const float* x    = (const float*)d_in[0];
    const float* ctrl = (const float*)d_in[1];
    const float* f1   = (const float*)d_in[2];
    const float* f2   = (const float*)d_in[3];
    const float* f1b  = (const float*)d_in[4];
    float* out = (float*)d_out;

    cudaFuncSetAttribute(ff1_mma_kernel, cudaFuncAttributeMaxDynamicSharedMemorySize, F1_SMEM);
    cudaFuncSetAttribute(ff2_mma_kernel, cudaFuncAttributeMaxDynamicSharedMemorySize, F2_SMEM);

    prologue_kernel<<<NB_ROUTER + 4096, 256>>>(x, ctrl, f1);
    router_fin_kernel<<<NG, 32>>>();
    ff1_mma_kernel<<<NB_FF1 + 4096, 256, F1_SMEM>>>(x, f1b, f2, out, out_size / 4);
    ff2_mma_kernel<<<dim3(NG / 128, DD / 128, NE), 256, F2_SMEM>>>(out);
}

// round 14
// speedup vs baseline: 1.0725x; 1.0725x over previous
#include <cuda_runtime.h>
#include <cuda_bf16.h>
#include <cstdint>

#define NG 512   // total groups
#define TG 32    // tokens per group
#define DD 1024  // model dim
#define NE 32    // experts
#define NS 128   // expert hidden size

__device__ float g_w[NG * NE];
__device__ int   g_sel[NG * NE];
__device__ float g_Lp[2 * NG * TG * NE];   // split-K partial logits
__device__ __nv_bfloat16 g_B1hi[(size_t)NE * NS * DD];
__device__ __nv_bfloat16 g_B1lo[(size_t)NE * NS * DD];
__device__ __nv_bfloat16 g_B2hi[(size_t)NE * DD * NS];
__device__ __nv_bfloat16 g_B2lo[(size_t)NE * DD * NS];
__device__ __nv_bfloat16 g_Ihi[(size_t)NE * NG * NS];
__device__ __nv_bfloat16 g_Ilo[(size_t)NE * NG * NS];

// ============================ helpers ============================
static __device__ __forceinline__ uint32_t smem_to_u32(const void* p) {
    uint32_t a;
    asm("{ .reg .u64 t; cvta.to.shared.u64 t, %1; cvt.u32.u64 %0, t; }"
        : "=r"(a) : "l"(p));
    return a;
}
static __device__ __forceinline__ void ldmat_x4(
    uint32_t& r0, uint32_t& r1, uint32_t& r2, uint32_t& r3, uint32_t addr)
{
    asm volatile("ldmatrix.sync.aligned.m8n8.x4.shared.b16 {%0,%1,%2,%3}, [%4];"
                 : "=r"(r0), "=r"(r1), "=r"(r2), "=r"(r3) : "r"(addr));
}
static __device__ __forceinline__ void mma16816(
    float* d, uint32_t a0, uint32_t a1, uint32_t a2, uint32_t a3,
    uint32_t b0, uint32_t b1)
{
    asm volatile("mma.sync.aligned.m16n8k16.row.col.f32.bf16.bf16.f32 "
                 "{%0,%1,%2,%3}, {%4,%5,%6,%7}, {%8,%9}, {%0,%1,%2,%3};"
                 : "+f"(d[0]), "+f"(d[1]), "+f"(d[2]), "+f"(d[3])
                 : "r"(a0), "r"(a1), "r"(a2), "r"(a3), "r"(b0), "r"(b1));
}
#define CP_ASYNC16(sm, gp) \
    asm volatile("cp.async.cg.shared.global [%0], [%1], 16;" :: "r"(sm), "l"(gp))
#define CP_COMMIT() asm volatile("cp.async.commit_group;" ::: "memory")
#define CP_WAIT0()  asm volatile("cp.async.wait_group 0;" ::: "memory")

static __device__ __forceinline__ unsigned long long pack2(float lo, float hi) {
    unsigned long long r;
    asm("mov.b64 %0, {%1, %2};" : "=l"(r) : "f"(lo), "f"(hi));
    return r;
}
static __device__ __forceinline__ void fma2(unsigned long long &d,
                                            unsigned long long a, unsigned long long b) {
    asm("fma.rn.f32x2 %0, %1, %2, %0;" : "+l"(d) : "l"(a), "l"(b));
}
static __device__ __forceinline__ float2 unpack2(unsigned long long v) {
    float lo, hi;
    asm("mov.b64 {%0, %1}, %2;" : "=f"(lo), "=f"(hi) : "l"(v));
    return make_float2(lo, hi);
}
static __device__ __forceinline__ void split_bf16(float v, __nv_bfloat16& h, __nv_bfloat16& l) {
    h = __float2bfloat16_rn(v);
    l = __float2bfloat16_rn(v - __bfloat162float(h));
}
static __device__ __forceinline__ uint32_t packbf(__nv_bfloat16 a, __nv_bfloat16 b) {
    __nv_bfloat162 p = __halves2bfloat162(a, b);
    return *(uint32_t*)&p;
}

// ---------------------------------------------------------------------------
// Prologue: blocks [0,512): router split-K partials; blocks [512, 4608):
// f1 transpose + bf16 split. (B2 prep + zero-fill live in ff1's grid.)
// ---------------------------------------------------------------------------
#define RT 64
#define RDC 64
#define XPAD 68
#define NB_ROUTER 512

__global__ __launch_bounds__(256) void prologue_kernel(
    const float* __restrict__ x, const float* __restrict__ ctrl,
    const float* __restrict__ f1)
{
    __shared__ __align__(16) float sm[RT * XPAD + RDC * NE];
    int b   = blockIdx.x;
    int tid = threadIdx.x;

    if (b < NB_ROUTER) {
        float* xs = sm;
        float (*cs)[NE] = (float(*)[NE])(sm + RT * XPAD);
        int tokbase = (b & 255) * RT;
        int khalf   = b >> 8;
        int kbase   = khalf * (DD / 2);

        int mt = (tid >> 3) << 1;
        int et = (tid & 7) << 2;

        unsigned long long acc[2][2];
        acc[0][0] = 0ULL; acc[0][1] = 0ULL; acc[1][0] = 0ULL; acc[1][1] = 0ULL;

        for (int dc = kbase; dc < kbase + DD / 2; dc += RDC) {
            __syncthreads();
#pragma unroll
            for (int it = 0; it < 4; it++) {
                int q  = tid + (it << 8);
                int t  = q >> 4;
                int d4 = (q & 15) << 2;
                *(float4*)&xs[t * XPAD + d4] =
                    *(const float4*)(x + (size_t)(tokbase + t) * DD + dc + d4);
            }
#pragma unroll
            for (int it = 0; it < 2; it++) {
                int q  = tid + (it << 8);
                int d  = q >> 3;
                int e4 = (q & 7) << 2;
                *(float4*)&cs[d][e4] = *(const float4*)(ctrl + (size_t)(dc + d) * NE + e4);
            }
            __syncthreads();
#pragma unroll 4
            for (int d = 0; d < RDC; d += 4) {
                float4 xr0 = *(const float4*)&xs[(mt    ) * XPAD + d];
                float4 xr1 = *(const float4*)&xs[(mt + 1) * XPAD + d];
#pragma unroll
                for (int dd = 0; dd < 4; dd++) {
                    ulonglong2 cb = *(const ulonglong2*)&cs[d + dd][et];
                    float v0 = (dd == 0) ? xr0.x : (dd == 1) ? xr0.y : (dd == 2) ? xr0.z : xr0.w;
                    float v1 = (dd == 0) ? xr1.x : (dd == 1) ? xr1.y : (dd == 2) ? xr1.z : xr1.w;
                    unsigned long long a0 = pack2(v0, v0);
                    unsigned long long a1 = pack2(v1, v1);
                    fma2(acc[0][0], a0, cb.x);
                    fma2(acc[0][1], a0, cb.y);
                    fma2(acc[1][0], a1, cb.x);
                    fma2(acc[1][1], a1, cb.y);
                }
            }
        }

        float* Lp = g_Lp + (size_t)khalf * (NG * TG * NE);
#pragma unroll
        for (int i = 0; i < 2; i++) {
            float2 v0 = unpack2(acc[i][0]);
            float2 v1 = unpack2(acc[i][1]);
            *(float4*)&Lp[(size_t)(tokbase + mt + i) * NE + et] =
                make_float4(v0.x, v0.y, v1.x, v1.y);
        }
    } else {
        // ----- f1 transpose + bf16 split -----
        int idx = b - NB_ROUTER;                  // 0..4095
        float (*tile)[33] = (float(*)[33])sm;
        int e  = idx >> 7;
        int kt = idx & 31;
        int nt = (idx >> 5) & 3;
        int tx = tid & 31, ty = tid >> 5;
#pragma unroll
        for (int r = 0; r < 4; r++) {
            int k = kt * 32 + ty + r * 8;
            tile[ty + r * 8][tx] = f1[((size_t)k * NE + e) * NS + nt * 32 + tx];
        }
        __syncthreads();
#pragma unroll
        for (int r = 0; r < 4; r++) {
            int n = nt * 32 + ty + r * 8;
            int k = kt * 32 + tx;
            float v = tile[tx][ty + r * 8];
            __nv_bfloat16 h, l;
            split_bf16(v, h, l);
            size_t ix = ((size_t)e * NS + n) * DD + k;
            g_B1hi[ix] = h;
            g_B1lo[ix] = l;
        }
    }
}

__global__ __launch_bounds__(32) void router_fin_kernel()
{
    int g = blockIdx.x;
    int e = threadIdx.x;
    const float* p0 = g_Lp + (size_t)(g * TG) * NE + e;
    const float* p1 = p0 + (size_t)NG * TG * NE;
    const float step = 1e-6f / 31.0f;

    float L[TG];
    float m = -1e30f;
    int am = 0;
#pragma unroll
    for (int t = 0; t < TG; t++) {
        float v = p0[t * NE] + p1[t * NE] + (float)t * step;
        L[t] = v;
        if (v > m) { m = v; am = t; }
    }
    float s = 0.f;
#pragma unroll
    for (int t = 0; t < TG; t++) s += __expf(L[t] - m);
    g_w[g * NE + e]   = 1.0f / s;
    g_sel[g * NE + e] = am;
}

// ---------------------------------------------------------------------------
// FF1 fused kernel (single wave):
//   blocks [0,256): GEMM  D[64g,128s] = (w*x[sel]) @ B1^T (3-term bf16 split)
//   blocks [256, 384): 128 prep blocks — each zeroes 512KB of out and
//   transposes/splits 32 f2 tiles (rides on idle DRAM while GEMM runs).
// ---------------------------------------------------------------------------
#define RS 80
#define F1_AH 0
#define F1_AL 5120
#define F1_BH 10240
#define F1_BL 20480
#define F1_BUF 30720
#define F1_SMEM (2 * F1_BUF)
#define NB_FF1 256
#define NB_PREP 128

__global__ __launch_bounds__(256, 3) void ff1_mma_kernel(
    const float* __restrict__ x, const float* __restrict__ f1b,
    const float* __restrict__ f2, float* __restrict__ out, int out_n4)
{
    extern __shared__ __align__(16) char smc[];
    int tid = threadIdx.x;
    int b   = blockIdx.x;

    if (b >= NB_FF1) {
        // ================= prep block: zero-fill + B2 transpose =================
        int idx = b - NB_FF1;                     // 0..127
        {
            float4 z = make_float4(0.f, 0.f, 0.f, 0.f);
            int base = idx * 32768 + tid;         // 128 blocks x 32768 f4 = out_n4
#pragma unroll 4
            for (int j = 0; j < 128; j++) {
                int i = base + j * 256;
                if (i < out_n4) ((float4*)out)[i] = z;
            }
        }
        float (*tile)[33] = (float(*)[33])smc;
        int tx = tid & 31, ty = tid >> 5;
        for (int t = 0; t < 32; t++) {
            int tl = idx * 32 + t;                // 0..4095
            int e  = tl >> 7;
            int dt = tl & 31;
            int st = (tl >> 5) & 3;
            __syncthreads();
#pragma unroll
            for (int r = 0; r < 4; r++) {
                int s = st * 32 + ty + r * 8;
                tile[ty + r * 8][tx] = f2[((size_t)e * NS + s) * DD + dt * 32 + tx];
            }
            __syncthreads();
#pragma unroll
            for (int r = 0; r < 4; r++) {
                int d = dt * 32 + ty + r * 8;
                int s = st * 32 + tx;
                float v = tile[tx][ty + r * 8];
                __nv_bfloat16 h, l;
                split_bf16(v, h, l);
                size_t ix = ((size_t)e * DD + d) * NS + s;
                g_B2hi[ix] = h;
                g_B2lo[ix] = l;
            }
        }
        return;
    }

    // ================= GEMM =================
    uint32_t smu = smem_to_u32(smc);
    int lane = tid & 31;
    int wid  = tid >> 5;
    int wm   = wid >> 2;     // 0..1
    int wn   = wid & 3;      // 0..3
    int e     = b >> 3;      // 0..31
    int gbase = (b & 7) * 64;

    int ar  = tid >> 2;
    int ac0 = (tid & 3) << 1;
    int gg  = gbase + ar;
    float wv = g_w[gg * NE + e];
    const float* arow = x + (size_t)(gg * TG + g_sel[gg * NE + e]) * DD;

    int br  = tid >> 1;
    int bh2 = tid & 1;
    const __nv_bfloat16* bhrow = g_B1hi + ((size_t)e * NS + br) * DD + bh2 * 16;
    const __nv_bfloat16* blrow = g_B1lo + ((size_t)e * NS + br) * DD + bh2 * 16;
    uint32_t bdst = smu + F1_BH + br * RS + bh2 * 32;

    float acc[2][4][4];
#pragma unroll
    for (int i = 0; i < 2; i++)
#pragma unroll
        for (int j = 0; j < 4; j++)
#pragma unroll
            for (int q = 0; q < 4; q++) acc[i][j][q] = 0.f;

    float4 pa[2];

#define FF1_FETCH_A(kt) do {                                                 \
        pa[0] = *(const float4*)(arow + (kt) + ac0 * 4);                     \
        pa[1] = *(const float4*)(arow + (kt) + ac0 * 4 + 4);                 \
    } while (0)

#define FF1_STORE_A(b_) do {                                                 \
        char* bb = smc + (b_) * F1_BUF;                                      \
        _Pragma("unroll")                                                    \
        for (int j = 0; j < 2; j++) {                                        \
            float4 v = pa[j];                                                \
            v.x *= wv; v.y *= wv; v.z *= wv; v.w *= wv;                      \
            __nv_bfloat16 h0,l0,h1,l1,h2,l2,h3,l3;                           \
            split_bf16(v.x,h0,l0); split_bf16(v.y,h1,l1);                    \
            split_bf16(v.z,h2,l2); split_bf16(v.w,h3,l3);                    \
            int off = ar * RS + (ac0 + j) * 8;                               \
            *(uint2*)(bb + F1_AH + off) = make_uint2(packbf(h0,h1), packbf(h2,h3)); \
            *(uint2*)(bb + F1_AL + off) = make_uint2(packbf(l0,l1), packbf(l2,l3)); \
        }                                                                    \
    } while (0)

#define FF1_CPASYNC_B(b_, kt) do {                                           \
        uint32_t d_ = bdst + (b_) * F1_BUF;                                  \
        CP_ASYNC16(d_,                      bhrow + (kt));                   \
        CP_ASYNC16(d_ + 16,                 bhrow + (kt) + 8);               \
        CP_ASYNC16(d_ + (F1_BL - F1_BH),      blrow + (kt));                 \
        CP_ASYNC16(d_ + (F1_BL - F1_BH) + 16, blrow + (kt) + 8);             \
    } while (0)

    FF1_FETCH_A(0);
    FF1_STORE_A(0);
    FF1_CPASYNC_B(0, 0);
    CP_COMMIT();

    int cur = 0;
    for (int it = 0; it < 32; it++) {
        bool more = (it + 1 < 32);
        CP_WAIT0();
        __syncthreads();
        if (more) {
            FF1_CPASYNC_B(cur ^ 1, (it + 1) * 32);
            CP_COMMIT();
            FF1_FETCH_A((it + 1) * 32);
        }
        uint32_t bufb = smu + cur * F1_BUF;
#pragma unroll
        for (int ksb = 0; ksb < 64; ksb += 32) {
            uint32_t bh_[4][2], bl_[4][2];
#pragma unroll
            for (int nb = 0; nb < 2; nb++) {
                uint32_t baddr = bufb + F1_BH +
                    (uint32_t)((wn * 32 + nb * 16 + (lane & 7) + ((lane >> 4) & 1) * 8) * RS +
                               ((lane >> 3) & 1) * 16 + ksb);
                ldmat_x4(bh_[2*nb][0], bh_[2*nb][1], bh_[2*nb+1][0], bh_[2*nb+1][1], baddr);
                ldmat_x4(bl_[2*nb][0], bl_[2*nb][1], bl_[2*nb+1][0], bl_[2*nb+1][1],
                         baddr + (F1_BL - F1_BH));
            }
#pragma unroll
            for (int mf = 0; mf < 2; mf++) {
                uint32_t aaddr = bufb + F1_AH +
                    (uint32_t)((wm * 32 + mf * 16 + (lane & 15)) * RS +
                               (lane >> 4) * 16 + ksb);
                uint32_t ah0, ah1, ah2, ah3, al0, al1, al2, al3;
                ldmat_x4(ah0, ah1, ah2, ah3, aaddr);
                ldmat_x4(al0, al1, al2, al3, aaddr + (F1_AL - F1_AH));
#pragma unroll
                for (int nf = 0; nf < 4; nf++)
                    mma16816(acc[mf][nf], ah0, ah1, ah2, ah3, bh_[nf][0], bh_[nf][1]);
#pragma unroll
                for (int nf = 0; nf < 4; nf++)
                    mma16816(acc[mf][nf], ah0, ah1, ah2, ah3, bl_[nf][0], bl_[nf][1]);
#pragma unroll
                for (int nf = 0; nf < 4; nf++)
                    mma16816(acc[mf][nf], al0, al1, al2, al3, bh_[nf][0], bh_[nf][1]);
            }
        }
        if (more) FF1_STORE_A(cur ^ 1);
        cur ^= 1;
    }

    const float* bias = f1b + e * NS;
#pragma unroll
    for (int mf = 0; mf < 2; mf++) {
#pragma unroll
        for (int nf = 0; nf < 4; nf++) {
            int c  = wn * 32 + nf * 8 + (lane & 3) * 2;
            float b0 = bias[c], b1 = bias[c + 1];
#pragma unroll
            for (int h = 0; h < 2; h++) {
                int r = wm * 32 + mf * 16 + (lane >> 2) + h * 8;
                float v0 = fmaxf(acc[mf][nf][2*h]     + b0, 0.f);
                float v1 = fmaxf(acc[mf][nf][2*h + 1] + b1, 0.f);
                __nv_bfloat16 h0, l0, h1, l1;
                split_bf16(v0, h0, l0); split_bf16(v1, h1, l1);
                size_t ob = ((size_t)e * NG + gbase + r) * NS + c;
                *(uint32_t*)&g_Ihi[ob] = packbf(h0, h1);
                *(uint32_t*)&g_Ilo[ob] = packbf(l0, l1);
            }
        }
    }
}

// ---------------------------------------------------------------------------
// FF2: D[128g,128d] = I[128,128s] x B2^T (3-term), scatter via red.v2.
// 256 threads, warp grid 2x4, warp tile 64x32, BK=32, double-buffered.
// ---------------------------------------------------------------------------
#define F2_AH 0
#define F2_AL 10240
#define F2_BH 20480
#define F2_BL 30720
#define F2_BUF 40960
#define F2_WV  (2 * F2_BUF)
#define F2_TOK (F2_WV + 512)
#define F2_SMEM (F2_TOK + 512)

__global__ __launch_bounds__(256) void ff2_mma_kernel(float* __restrict__ out)
{
    extern __shared__ __align__(16) char smc[];
    uint32_t smu = smem_to_u32(smc);
    int tid  = threadIdx.x;
    int lane = tid & 31;
    int wid  = tid >> 5;
    int wm   = wid >> 2;
    int wn   = wid & 3;
    int e     = blockIdx.z;
    int gbase = blockIdx.x * 128;
    int nbase = blockIdx.y * 128;

    float* swv = (float*)(smc + F2_WV);
    int*   stok = (int*)(smc + F2_TOK);
    if (tid < 128) {
        int g = gbase + tid;
        swv[tid]  = g_w[g * NE + e];
        stok[tid] = g * TG + g_sel[g * NE + e];
    }

    int r_  = tid >> 1;
    int h2  = tid & 1;
    const __nv_bfloat16* ahrow = g_Ihi + ((size_t)e * NG + gbase + r_) * NS + h2 * 16;
    const __nv_bfloat16* alrow = g_Ilo + ((size_t)e * NG + gbase + r_) * NS + h2 * 16;
    const __nv_bfloat16* bhrow = g_B2hi + ((size_t)e * DD + nbase + r_) * NS + h2 * 16;
    const __nv_bfloat16* blrow = g_B2lo + ((size_t)e * DD + nbase + r_) * NS + h2 * 16;
    uint32_t adst = smu + F2_AH + r_ * RS + h2 * 32;
    uint32_t bdst = smu + F2_BH + r_ * RS + h2 * 32;

    float acc[4][4][4];
#pragma unroll
    for (int i = 0; i < 4; i++)
#pragma unroll
        for (int j = 0; j < 4; j++)
#pragma unroll
            for (int q = 0; q < 4; q++) acc[i][j][q] = 0.f;

#define FF2_CPASYNC(b_, kt) do {                                             \
        uint32_t ad_ = adst + (b_) * F2_BUF;                                 \
        uint32_t bd_ = bdst + (b_) * F2_BUF;                                 \
        CP_ASYNC16(ad_,                       ahrow + (kt));                 \
        CP_ASYNC16(ad_ + 16,                  ahrow + (kt) + 8);             \
        CP_ASYNC16(ad_ + (F2_AL - F2_AH),      alrow + (kt));                \
        CP_ASYNC16(ad_ + (F2_AL - F2_AH) + 16, alrow + (kt) + 8);            \
        CP_ASYNC16(bd_,                       bhrow + (kt));                 \
        CP_ASYNC16(bd_ + 16,                  bhrow + (kt) + 8);             \
        CP_ASYNC16(bd_ + (F2_BL - F2_BH),      blrow + (kt));                \
        CP_ASYNC16(bd_ + (F2_BL - F2_BH) + 16, blrow + (kt) + 8);            \
    } while (0)

    FF2_CPASYNC(0, 0);
    CP_COMMIT();

    int cur = 0;
    for (int it = 0; it < 4; it++) {
        bool more = (it + 1 < 4);
        CP_WAIT0();
        __syncthreads();
        if (more) {
            FF2_CPASYNC(cur ^ 1, (it + 1) * 32);
            CP_COMMIT();
        }
        uint32_t bufb = smu + cur * F2_BUF;
#pragma unroll
        for (int ksb = 0; ksb < 64; ksb += 32) {
            uint32_t bh_[4][2], bl_[4][2];
#pragma unroll
            for (int nb = 0; nb < 2; nb++) {
                uint32_t baddr = bufb + F2_BH +
                    (uint32_t)((wn * 32 + nb * 16 + (lane & 7) + ((lane >> 4) & 1) * 8) * RS +
                               ((lane >> 3) & 1) * 16 + ksb);
                ldmat_x4(bh_[2*nb][0], bh_[2*nb][1], bh_[2*nb+1][0], bh_[2*nb+1][1], baddr);
                ldmat_x4(bl_[2*nb][0], bl_[2*nb][1], bl_[2*nb+1][0], bl_[2*nb+1][1],
                         baddr + (F2_BL - F2_BH));
            }
#pragma unroll
            for (int mf = 0; mf < 4; mf++) {
                uint32_t aaddr = bufb + F2_AH +
                    (uint32_t)((wm * 64 + mf * 16 + (lane & 15)) * RS +
                               (lane >> 4) * 16 + ksb);
                uint32_t ah0, ah1, ah2, ah3, al0, al1, al2, al3;
                ldmat_x4(ah0, ah1, ah2, ah3, aaddr);
                ldmat_x4(al0, al1, al2, al3, aaddr + (F2_AL - F2_AH));
#pragma unroll
                for (int nf = 0; nf < 4; nf++)
                    mma16816(acc[mf][nf], ah0, ah1, ah2, ah3, bh_[nf][0], bh_[nf][1]);
#pragma unroll
                for (int nf = 0; nf < 4; nf++)
                    mma16816(acc[mf][nf], ah0, ah1, ah2, ah3, bl_[nf][0], bl_[nf][1]);
#pragma unroll
                for (int nf = 0; nf < 4; nf++)
                    mma16816(acc[mf][nf], al0, al1, al2, al3, bh_[nf][0], bh_[nf][1]);
            }
        }
        cur ^= 1;
    }

#pragma unroll
    for (int mf = 0; mf < 4; mf++) {
#pragma unroll
        for (int nf = 0; nf < 4; nf++) {
            int c = wn * 32 + nf * 8 + (lane & 3) * 2;
#pragma unroll
            for (int h = 0; h < 2; h++) {
                int r = wm * 64 + mf * 16 + (lane >> 2) + h * 8;
                float wv = swv[r];
                float* p = out + (size_t)stok[r] * DD + nbase + c;
                float v0 = wv * acc[mf][nf][2*h];
                float v1 = wv * acc[mf][nf][2*h + 1];
                asm volatile("red.global.add.v2.f32 [%0], {%1, %2};"
                             :: "l"(p), "f"(v0), "f"(v1) : "memory");
            }
        }
    }
}

// ---------------------------------------------------------------------------
extern "C" void kernel_launch(void* const* d_in, const int* in_sizes, int n_in,
                              void* d_out, int out_size) {
    const float* x    = (const float*)d_in[0];
    const float* ctrl = (const float*)d_in[1];
    const float* f1   = (const float*)d_in[2];
    const float* f2   = (const float*)d_in[3];
    const float* f1b  = (const float*)d_in[4];
    float* out = (float*)d_out;

    cudaFuncSetAttribute(ff1_mma_kernel, cudaFuncAttributeMaxDynamicSharedMemorySize, F1_SMEM);
    cudaFuncSetAttribute(ff2_mma_kernel, cudaFuncAttributeMaxDynamicSharedMemorySize, F2_SMEM);

    prologue_kernel<<<NB_ROUTER + 4096, 256>>>(x, ctrl, f1);
    router_fin_kernel<<<NG, 32>>>();
    ff1_mma_kernel<<<NB_FF1 + NB_PREP, 256, F1_SMEM>>>(x, f1b, f2, out, out_size / 4);
    ff2_mma_kernel<<<dim3(NG / 128, DD / 128, NE), 256, F2_SMEM>>>(out);
}

// round 15
// speedup vs baseline: 1.0786x; 1.0057x over previous
#include <cuda_runtime.h>
#include <cuda_bf16.h>
#include <cstdint>

#define NG 512   // total groups
#define TG 32    // tokens per group
#define DD 1024  // model dim
#define NE 32    // experts
#define NS 128   // expert hidden size

__device__ float g_w[NG * NE];
__device__ int   g_sel[NG * NE];
__device__ float g_Lp[2 * NG * TG * NE];   // split-K partial logits
__device__ unsigned g_done[NE];            // ff1 per-expert completion counters
__device__ __nv_bfloat16 g_B1hi[(size_t)NE * NS * DD];
__device__ __nv_bfloat16 g_B1lo[(size_t)NE * NS * DD];
__device__ __nv_bfloat16 g_B2hi[(size_t)NE * DD * NS];
__device__ __nv_bfloat16 g_B2lo[(size_t)NE * DD * NS];
__device__ __nv_bfloat16 g_Ihi[(size_t)NE * NG * NS];
__device__ __nv_bfloat16 g_Ilo[(size_t)NE * NG * NS];

// ============================ helpers ============================
static __device__ __forceinline__ uint32_t smem_to_u32(const void* p) {
    uint32_t a;
    asm("{ .reg .u64 t; cvta.to.shared.u64 t, %1; cvt.u32.u64 %0, t; }"
        : "=r"(a) : "l"(p));
    return a;
}
static __device__ __forceinline__ void ldmat_x4(
    uint32_t& r0, uint32_t& r1, uint32_t& r2, uint32_t& r3, uint32_t addr)
{
    asm volatile("ldmatrix.sync.aligned.m8n8.x4.shared.b16 {%0,%1,%2,%3}, [%4];"
                 : "=r"(r0), "=r"(r1), "=r"(r2), "=r"(r3) : "r"(addr));
}
static __device__ __forceinline__ void mma16816(
    float* d, uint32_t a0, uint32_t a1, uint32_t a2, uint32_t a3,
    uint32_t b0, uint32_t b1)
{
    asm volatile("mma.sync.aligned.m16n8k16.row.col.f32.bf16.bf16.f32 "
                 "{%0,%1,%2,%3}, {%4,%5,%6,%7}, {%8,%9}, {%0,%1,%2,%3};"
                 : "+f"(d[0]), "+f"(d[1]), "+f"(d[2]), "+f"(d[3])
                 : "r"(a0), "r"(a1), "r"(a2), "r"(a3), "r"(b0), "r"(b1));
}
#define CP_ASYNC16(sm, gp) \
    asm volatile("cp.async.cg.shared.global [%0], [%1], 16;" :: "r"(sm), "l"(gp))
#define CP_COMMIT() asm volatile("cp.async.commit_group;" ::: "memory")
#define CP_WAIT0()  asm volatile("cp.async.wait_group 0;" ::: "memory")

static __device__ __forceinline__ unsigned long long pack2(float lo, float hi) {
    unsigned long long r;
    asm("mov.b64 %0, {%1, %2};" : "=l"(r) : "f"(lo), "f"(hi));
    return r;
}
static __device__ __forceinline__ void fma2(unsigned long long &d,
                                            unsigned long long a, unsigned long long b) {
    asm("fma.rn.f32x2 %0, %1, %2, %0;" : "+l"(d) : "l"(a), "l"(b));
}
static __device__ __forceinline__ float2 unpack2(unsigned long long v) {
    float lo, hi;
    asm("mov.b64 {%0, %1}, %2;" : "=f"(lo), "=f"(hi) : "l"(v));
    return make_float2(lo, hi);
}
static __device__ __forceinline__ void split_bf16(float v, __nv_bfloat16& h, __nv_bfloat16& l) {
    h = __float2bfloat16_rn(v);
    l = __float2bfloat16_rn(v - __bfloat162float(h));
}
static __device__ __forceinline__ uint32_t packbf(__nv_bfloat16 a, __nv_bfloat16 b) {
    __nv_bfloat162 p = __halves2bfloat162(a, b);
    return *(uint32_t*)&p;
}

// ---------------------------------------------------------------------------
// Prologue: blocks [0,512): router split-K partials; blocks [512, 8704):
// weight transpose + bf16 split + out zero-fill slice.  (round-9 version)
// ---------------------------------------------------------------------------
#define RT 64
#define RDC 64
#define XPAD 68
#define NB_ROUTER 512

__global__ __launch_bounds__(256) void prologue_kernel(
    const float* __restrict__ x, const float* __restrict__ ctrl,
    const float* __restrict__ f1, const float* __restrict__ f2,
    float* __restrict__ out, int out_n4)
{
    __shared__ __align__(16) float sm[RT * XPAD + RDC * NE];
    int b   = blockIdx.x;
    int tid = threadIdx.x;

    if (b < NB_ROUTER) {
        float* xs = sm;
        float (*cs)[NE] = (float(*)[NE])(sm + RT * XPAD);
        int tokbase = (b & 255) * RT;
        int khalf   = b >> 8;
        int kbase   = khalf * (DD / 2);

        int mt = (tid >> 3) << 1;
        int et = (tid & 7) << 2;

        unsigned long long acc[2][2];
        acc[0][0] = 0ULL; acc[0][1] = 0ULL; acc[1][0] = 0ULL; acc[1][1] = 0ULL;

        for (int dc = kbase; dc < kbase + DD / 2; dc += RDC) {
            __syncthreads();
#pragma unroll
            for (int it = 0; it < 4; it++) {
                int q  = tid + (it << 8);
                int t  = q >> 4;
                int d4 = (q & 15) << 2;
                *(float4*)&xs[t * XPAD + d4] =
                    *(const float4*)(x + (size_t)(tokbase + t) * DD + dc + d4);
            }
#pragma unroll
            for (int it = 0; it < 2; it++) {
                int q  = tid + (it << 8);
                int d  = q >> 3;
                int e4 = (q & 7) << 2;
                *(float4*)&cs[d][e4] = *(const float4*)(ctrl + (size_t)(dc + d) * NE + e4);
            }
            __syncthreads();
#pragma unroll 4
            for (int d = 0; d < RDC; d += 4) {
                float4 xr0 = *(const float4*)&xs[(mt    ) * XPAD + d];
                float4 xr1 = *(const float4*)&xs[(mt + 1) * XPAD + d];
#pragma unroll
                for (int dd = 0; dd < 4; dd++) {
                    ulonglong2 cb = *(const ulonglong2*)&cs[d + dd][et];
                    float v0 = (dd == 0) ? xr0.x : (dd == 1) ? xr0.y : (dd == 2) ? xr0.z : xr0.w;
                    float v1 = (dd == 0) ? xr1.x : (dd == 1) ? xr1.y : (dd == 2) ? xr1.z : xr1.w;
                    unsigned long long a0 = pack2(v0, v0);
                    unsigned long long a1 = pack2(v1, v1);
                    fma2(acc[0][0], a0, cb.x);
                    fma2(acc[0][1], a0, cb.y);
                    fma2(acc[1][0], a1, cb.x);
                    fma2(acc[1][1], a1, cb.y);
                }
            }
        }

        float* Lp = g_Lp + (size_t)khalf * (NG * TG * NE);
#pragma unroll
        for (int i = 0; i < 2; i++) {
            float2 v0 = unpack2(acc[i][0]);
            float2 v1 = unpack2(acc[i][1]);
            *(float4*)&Lp[(size_t)(tokbase + mt + i) * NE + et] =
                make_float4(v0.x, v0.y, v1.x, v1.y);
        }
    } else {
        int idx = b - NB_ROUTER;                  // 0..8191
        {
            float4 z = make_float4(0.f, 0.f, 0.f, 0.f);
            int base = idx * 512 + tid;
            if (base < out_n4)       ((float4*)out)[base] = z;
            if (base + 256 < out_n4) ((float4*)out)[base + 256] = z;
        }
        float (*tile)[33] = (float(*)[33])sm;
        int z_  = idx >> 7;          // 0..63
        int bi  = idx & 31;
        int bj  = (idx >> 5) & 3;
        int tx  = tid & 31, ty = tid >> 5;
        if (z_ < 32) {
            int e = z_, nt = bj, kt = bi;
#pragma unroll
            for (int r = 0; r < 4; r++) {
                int k = kt * 32 + ty + r * 8;
                tile[ty + r * 8][tx] = f1[((size_t)k * NE + e) * NS + nt * 32 + tx];
            }
            __syncthreads();
#pragma unroll
            for (int r = 0; r < 4; r++) {
                int n = nt * 32 + ty + r * 8;
                int k = kt * 32 + tx;
                float v = tile[tx][ty + r * 8];
                __nv_bfloat16 h, l;
                split_bf16(v, h, l);
                size_t ix = ((size_t)e * NS + n) * DD + k;
                g_B1hi[ix] = h;
                g_B1lo[ix] = l;
            }
        } else {
            int e = z_ - 32, st = bj, dt = bi;
#pragma unroll
            for (int r = 0; r < 4; r++) {
                int s = st * 32 + ty + r * 8;
                tile[ty + r * 8][tx] = f2[((size_t)e * NS + s) * DD + dt * 32 + tx];
            }
            __syncthreads();
#pragma unroll
            for (int r = 0; r < 4; r++) {
                int d = dt * 32 + ty + r * 8;
                int s = st * 32 + tx;
                float v = tile[tx][ty + r * 8];
                __nv_bfloat16 h, l;
                split_bf16(v, h, l);
                size_t ix = ((size_t)e * DD + d) * NS + s;
                g_B2hi[ix] = h;
                g_B2lo[ix] = l;
            }
        }
    }
}

// Router finalize + reset g_done counters (block 0).
__global__ __launch_bounds__(32) void router_fin_kernel()
{
    int g = blockIdx.x;
    int e = threadIdx.x;
    if (g == 0) g_done[e] = 0u;

    const float* p0 = g_Lp + (size_t)(g * TG) * NE + e;
    const float* p1 = p0 + (size_t)NG * TG * NE;
    const float step = 1e-6f / 31.0f;

    float L[TG];
    float m = -1e30f;
    int am = 0;
#pragma unroll
    for (int t = 0; t < TG; t++) {
        float v = p0[t * NE] + p1[t * NE] + (float)t * step;
        L[t] = v;
        if (v > m) { m = v; am = t; }
    }
    float s = 0.f;
#pragma unroll
    for (int t = 0; t < TG; t++) s += __expf(L[t] - m);
    g_w[g * NE + e]   = 1.0f / s;
    g_sel[g * NE + e] = am;
}

// ---------------------------------------------------------------------------
// Fused FF kernel:
//   blocks [0,256): ff1 role — D[64g,128s]=(w*x[sel])@B1^T, writes g_I,
//                   then release-increments g_done[e].
//   blocks [256,1280): ff2 role — spins until g_done[e]==8, then
//                   D[128g,128d]=I@B2^T, scatter via red.v2.
//   ff2 blocks ordered by ascending expert to match ff1 completion order.
// ---------------------------------------------------------------------------
#define RS 80
#define F1_AH 0
#define F1_AL 5120
#define F1_BH 10240
#define F1_BL 20480
#define F1_BUF 30720
#define F2_AH 0
#define F2_AL 10240
#define F2_BH 20480
#define F2_BL 30720
#define F2_BUF 40960
#define F2_WV  (2 * F2_BUF)
#define F2_TOK (F2_WV + 512)
#define FF_SMEM (F2_TOK + 512)
#define NB_FF1 256

__global__ __launch_bounds__(256) void fused_ff_kernel(
    const float* __restrict__ x, const float* __restrict__ f1b,
    float* __restrict__ out)
{
    extern __shared__ __align__(16) char smc[];
    uint32_t smu = smem_to_u32(smc);
    int tid  = threadIdx.x;
    int lane = tid & 31;
    int wid  = tid >> 5;
    int wm   = wid >> 2;
    int wn   = wid & 3;
    int b    = blockIdx.x;

    if (b < NB_FF1) {
        // ========================= FF1 role =========================
        int e     = b >> 3;
        int gbase = (b & 7) * 64;

        int ar  = tid >> 2;
        int ac0 = (tid & 3) << 1;
        int gg  = gbase + ar;
        float wv = g_w[gg * NE + e];
        const float* arow = x + (size_t)(gg * TG + g_sel[gg * NE + e]) * DD;

        int br  = tid >> 1;
        int bh2 = tid & 1;
        const __nv_bfloat16* bhrow = g_B1hi + ((size_t)e * NS + br) * DD + bh2 * 16;
        const __nv_bfloat16* blrow = g_B1lo + ((size_t)e * NS + br) * DD + bh2 * 16;
        uint32_t bdst = smu + F1_BH + br * RS + bh2 * 32;

        float acc[2][4][4];
#pragma unroll
        for (int i = 0; i < 2; i++)
#pragma unroll
            for (int j = 0; j < 4; j++)
#pragma unroll
                for (int q = 0; q < 4; q++) acc[i][j][q] = 0.f;

        float4 pa[2];

#define FF1_FETCH_A(kt) do {                                                 \
        pa[0] = *(const float4*)(arow + (kt) + ac0 * 4);                     \
        pa[1] = *(const float4*)(arow + (kt) + ac0 * 4 + 4);                 \
    } while (0)

#define FF1_STORE_A(b_) do {                                                 \
        char* bb = smc + (b_) * F1_BUF;                                      \
        _Pragma("unroll")                                                    \
        for (int j = 0; j < 2; j++) {                                        \
            float4 v = pa[j];                                                \
            v.x *= wv; v.y *= wv; v.z *= wv; v.w *= wv;                      \
            __nv_bfloat16 h0,l0,h1,l1,h2,l2,h3,l3;                           \
            split_bf16(v.x,h0,l0); split_bf16(v.y,h1,l1);                    \
            split_bf16(v.z,h2,l2); split_bf16(v.w,h3,l3);                    \
            int off = ar * RS + (ac0 + j) * 8;                               \
            *(uint2*)(bb + F1_AH + off) = make_uint2(packbf(h0,h1), packbf(h2,h3)); \
            *(uint2*)(bb + F1_AL + off) = make_uint2(packbf(l0,l1), packbf(l2,l3)); \
        }                                                                    \
    } while (0)

#define FF1_CPASYNC_B(b_, kt) do {                                           \
        uint32_t d_ = bdst + (b_) * F1_BUF;                                  \
        CP_ASYNC16(d_,                      bhrow + (kt));                   \
        CP_ASYNC16(d_ + 16,                 bhrow + (kt) + 8);               \
        CP_ASYNC16(d_ + (F1_BL - F1_BH),      blrow + (kt));                 \
        CP_ASYNC16(d_ + (F1_BL - F1_BH) + 16, blrow + (kt) + 8);             \
    } while (0)

        FF1_FETCH_A(0);
        FF1_STORE_A(0);
        FF1_CPASYNC_B(0, 0);
        CP_COMMIT();

        int cur = 0;
        for (int it = 0; it < 32; it++) {
            bool more = (it + 1 < 32);
            CP_WAIT0();
            __syncthreads();
            if (more) {
                FF1_CPASYNC_B(cur ^ 1, (it + 1) * 32);
                CP_COMMIT();
                FF1_FETCH_A((it + 1) * 32);
            }
            uint32_t bufb = smu + cur * F1_BUF;
#pragma unroll
            for (int ksb = 0; ksb < 64; ksb += 32) {
                uint32_t bh_[4][2], bl_[4][2];
#pragma unroll
                for (int nb = 0; nb < 2; nb++) {
                    uint32_t baddr = bufb + F1_BH +
                        (uint32_t)((wn * 32 + nb * 16 + (lane & 7) + ((lane >> 4) & 1) * 8) * RS +
                                   ((lane >> 3) & 1) * 16 + ksb);
                    ldmat_x4(bh_[2*nb][0], bh_[2*nb][1], bh_[2*nb+1][0], bh_[2*nb+1][1], baddr);
                    ldmat_x4(bl_[2*nb][0], bl_[2*nb][1], bl_[2*nb+1][0], bl_[2*nb+1][1],
                             baddr + (F1_BL - F1_BH));
                }
#pragma unroll
                for (int mf = 0; mf < 2; mf++) {
                    uint32_t aaddr = bufb + F1_AH +
                        (uint32_t)((wm * 32 + mf * 16 + (lane & 15)) * RS +
                                   (lane >> 4) * 16 + ksb);
                    uint32_t ah0, ah1, ah2, ah3, al0, al1, al2, al3;
                    ldmat_x4(ah0, ah1, ah2, ah3, aaddr);
                    ldmat_x4(al0, al1, al2, al3, aaddr + (F1_AL - F1_AH));
#pragma unroll
                    for (int nf = 0; nf < 4; nf++)
                        mma16816(acc[mf][nf], ah0, ah1, ah2, ah3, bh_[nf][0], bh_[nf][1]);
#pragma unroll
                    for (int nf = 0; nf < 4; nf++)
                        mma16816(acc[mf][nf], ah0, ah1, ah2, ah3, bl_[nf][0], bl_[nf][1]);
#pragma unroll
                    for (int nf = 0; nf < 4; nf++)
                        mma16816(acc[mf][nf], al0, al1, al2, al3, bh_[nf][0], bh_[nf][1]);
                }
            }
            if (more) FF1_STORE_A(cur ^ 1);
            cur ^= 1;
        }

        const float* bias = f1b + e * NS;
#pragma unroll
        for (int mf = 0; mf < 2; mf++) {
#pragma unroll
            for (int nf = 0; nf < 4; nf++) {
                int c  = wn * 32 + nf * 8 + (lane & 3) * 2;
                float b0 = bias[c], b1 = bias[c + 1];
#pragma unroll
                for (int h = 0; h < 2; h++) {
                    int r = wm * 32 + mf * 16 + (lane >> 2) + h * 8;
                    float v0 = fmaxf(acc[mf][nf][2*h]     + b0, 0.f);
                    float v1 = fmaxf(acc[mf][nf][2*h + 1] + b1, 0.f);
                    __nv_bfloat16 h0, l0, h1, l1;
                    split_bf16(v0, h0, l0); split_bf16(v1, h1, l1);
                    size_t ob = ((size_t)e * NG + gbase + r) * NS + c;
                    *(uint32_t*)&g_Ihi[ob] = packbf(h0, h1);
                    *(uint32_t*)&g_Ilo[ob] = packbf(l0, l1);
                }
            }
        }
        // release: make I visible, then signal
        __threadfence();
        __syncthreads();
        if (tid == 0) atomicAdd(&g_done[e], 1u);
        return;
    }

    // ========================= FF2 role =========================
    int id = b - NB_FF1;              // 0..1023, expert-major
    int e  = id >> 5;
    int gbase = ((id >> 3) & 3) * 128;
    int nbase = (id & 7) * 128;

    // wait for this expert's I tiles
    if (tid == 0) {
        while (*(volatile unsigned*)&g_done[e] < 8u) __nanosleep(200);
    }
    __syncthreads();
    __threadfence();

    float* swv = (float*)(smc + F2_WV);
    int*   stok = (int*)(smc + F2_TOK);
    if (tid < 128) {
        int g = gbase + tid;
        swv[tid]  = g_w[g * NE + e];
        stok[tid] = g * TG + g_sel[g * NE + e];
    }

    int r_  = tid >> 1;
    int h2  = tid & 1;
    const __nv_bfloat16* ahrow = g_Ihi + ((size_t)e * NG + gbase + r_) * NS + h2 * 16;
    const __nv_bfloat16* alrow = g_Ilo + ((size_t)e * NG + gbase + r_) * NS + h2 * 16;
    const __nv_bfloat16* bhrow = g_B2hi + ((size_t)e * DD + nbase + r_) * NS + h2 * 16;
    const __nv_bfloat16* blrow = g_B2lo + ((size_t)e * DD + nbase + r_) * NS + h2 * 16;
    uint32_t adst = smu + F2_AH + r_ * RS + h2 * 32;
    uint32_t bdst = smu + F2_BH + r_ * RS + h2 * 32;

    float acc[4][4][4];
#pragma unroll
    for (int i = 0; i < 4; i++)
#pragma unroll
        for (int j = 0; j < 4; j++)
#pragma unroll
            for (int q = 0; q < 4; q++) acc[i][j][q] = 0.f;

#define FF2_CPASYNC(b_, kt) do {                                             \
        uint32_t ad_ = adst + (b_) * F2_BUF;                                 \
        uint32_t bd_ = bdst + (b_) * F2_BUF;                                 \
        CP_ASYNC16(ad_,                       ahrow + (kt));                 \
        CP_ASYNC16(ad_ + 16,                  ahrow + (kt) + 8);             \
        CP_ASYNC16(ad_ + (F2_AL - F2_AH),      alrow + (kt));                \
        CP_ASYNC16(ad_ + (F2_AL - F2_AH) + 16, alrow + (kt) + 8);            \
        CP_ASYNC16(bd_,                       bhrow + (kt));                 \
        CP_ASYNC16(bd_ + 16,                  bhrow + (kt) + 8);             \
        CP_ASYNC16(bd_ + (F2_BL - F2_BH),      blrow + (kt));                \
        CP_ASYNC16(bd_ + (F2_BL - F2_BH) + 16, blrow + (kt) + 8);            \
    } while (0)

    FF2_CPASYNC(0, 0);
    CP_COMMIT();

    int cur = 0;
    for (int it = 0; it < 4; it++) {
        bool more = (it + 1 < 4);
        CP_WAIT0();
        __syncthreads();
        if (more) {
            FF2_CPASYNC(cur ^ 1, (it + 1) * 32);
            CP_COMMIT();
        }
        uint32_t bufb = smu + cur * F2_BUF;
#pragma unroll
        for (int ksb = 0; ksb < 64; ksb += 32) {
            uint32_t bh_[4][2], bl_[4][2];
#pragma unroll
            for (int nb = 0; nb < 2; nb++) {
                uint32_t baddr = bufb + F2_BH +
                    (uint32_t)((wn * 32 + nb * 16 + (lane & 7) + ((lane >> 4) & 1) * 8) * RS +
                               ((lane >> 3) & 1) * 16 + ksb);
                ldmat_x4(bh_[2*nb][0], bh_[2*nb][1], bh_[2*nb+1][0], bh_[2*nb+1][1], baddr);
                ldmat_x4(bl_[2*nb][0], bl_[2*nb][1], bl_[2*nb+1][0], bl_[2*nb+1][1],
                         baddr + (F2_BL - F2_BH));
            }
#pragma unroll
            for (int mf = 0; mf < 4; mf++) {
                uint32_t aaddr = bufb + F2_AH +
                    (uint32_t)((wm * 64 + mf * 16 + (lane & 15)) * RS +
                               (lane >> 4) * 16 + ksb);
                uint32_t ah0, ah1, ah2, ah3, al0, al1, al2, al3;
                ldmat_x4(ah0, ah1, ah2, ah3, aaddr);
                ldmat_x4(al0, al1, al2, al3, aaddr + (F2_AL - F2_AH));
#pragma unroll
                for (int nf = 0; nf < 4; nf++)
                    mma16816(acc[mf][nf], ah0, ah1, ah2, ah3, bh_[nf][0], bh_[nf][1]);
#pragma unroll
                for (int nf = 0; nf < 4; nf++)
                    mma16816(acc[mf][nf], ah0, ah1, ah2, ah3, bl_[nf][0], bl_[nf][1]);
#pragma unroll
                for (int nf = 0; nf < 4; nf++)
                    mma16816(acc[mf][nf], al0, al1, al2, al3, bh_[nf][0], bh_[nf][1]);
            }
        }
        cur ^= 1;
    }

#pragma unroll
    for (int mf = 0; mf < 4; mf++) {
#pragma unroll
        for (int nf = 0; nf < 4; nf++) {
            int c = wn * 32 + nf * 8 + (lane & 3) * 2;
#pragma unroll
            for (int h = 0; h < 2; h++) {
                int r = wm * 64 + mf * 16 + (lane >> 2) + h * 8;
                float wv = swv[r];
                float* p = out + (size_t)stok[r] * DD + nbase + c;
                float v0 = wv * acc[mf][nf][2*h];
                float v1 = wv * acc[mf][nf][2*h + 1];
                asm volatile("red.global.add.v2.f32 [%0], {%1, %2};"
                             :: "l"(p), "f"(v0), "f"(v1) : "memory");
            }
        }
    }
}

// ---------------------------------------------------------------------------
extern "C" void kernel_launch(void* const* d_in, const int* in_sizes, int n_in,
                              void* d_out, int out_size) {
    const float* x    = (const float*)d_in[0];
    const float* ctrl = (const float*)d_in[1];
    const float* f1   = (const float*)d_in[2];
    const float* f2   = (const float*)d_in[3];
    const float* f1b  = (const float*)d_in[4];
    float* out = (float*)d_out;

    cudaFuncSetAttribute(fused_ff_kernel, cudaFuncAttributeMaxDynamicSharedMemorySize, FF_SMEM);

    prologue_kernel<<<NB_ROUTER + 8192, 256>>>(x, ctrl, f1, f2, out, out_size / 4);
    router_fin_kernel<<<NG, 32>>>();
    fused_ff_kernel<<<NB_FF1 + 1024, 256, FF_SMEM>>>(x, f1b, out);
}

// round 16
// speedup vs baseline: 1.0790x; 1.0004x over previous
#include <cuda_runtime.h>
#include <cuda_bf16.h>
#include <cstdint>

#define NG 512   // total groups
#define TG 32    // tokens per group
#define DD 1024  // model dim
#define NE 32    // experts
#define NS 128   // expert hidden size

__device__ float g_w[NG * NE];
__device__ int   g_sel[NG * NE];
__device__ float g_Lp[2 * NG * TG * NE];   // split-K partial logits
__device__ unsigned g_done[NE];            // ff1 per-expert completion counters
__device__ unsigned g_zero;                // out zero-fill completion counter
__device__ __nv_bfloat16 g_B1hi[(size_t)NE * NS * DD];
__device__ __nv_bfloat16 g_B1lo[(size_t)NE * NS * DD];
__device__ __nv_bfloat16 g_B2hi[(size_t)NE * DD * NS];
__device__ __nv_bfloat16 g_B2lo[(size_t)NE * DD * NS];
__device__ __nv_bfloat16 g_Ihi[(size_t)NE * NG * NS];
__device__ __nv_bfloat16 g_Ilo[(size_t)NE * NG * NS];

// ============================ helpers ============================
static __device__ __forceinline__ uint32_t smem_to_u32(const void* p) {
    uint32_t a;
    asm("{ .reg .u64 t; cvta.to.shared.u64 t, %1; cvt.u32.u64 %0, t; }"
        : "=r"(a) : "l"(p));
    return a;
}
static __device__ __forceinline__ void ldmat_x4(
    uint32_t& r0, uint32_t& r1, uint32_t& r2, uint32_t& r3, uint32_t addr)
{
    asm volatile("ldmatrix.sync.aligned.m8n8.x4.shared.b16 {%0,%1,%2,%3}, [%4];"
                 : "=r"(r0), "=r"(r1), "=r"(r2), "=r"(r3) : "r"(addr));
}
static __device__ __forceinline__ void mma16816(
    float* d, uint32_t a0, uint32_t a1, uint32_t a2, uint32_t a3,
    uint32_t b0, uint32_t b1)
{
    asm volatile("mma.sync.aligned.m16n8k16.row.col.f32.bf16.bf16.f32 "
                 "{%0,%1,%2,%3}, {%4,%5,%6,%7}, {%8,%9}, {%0,%1,%2,%3};"
                 : "+f"(d[0]), "+f"(d[1]), "+f"(d[2]), "+f"(d[3])
                 : "r"(a0), "r"(a1), "r"(a2), "r"(a3), "r"(b0), "r"(b1));
}
#define CP_ASYNC16(sm, gp) \
    asm volatile("cp.async.cg.shared.global [%0], [%1], 16;" :: "r"(sm), "l"(gp))
#define CP_COMMIT() asm volatile("cp.async.commit_group;" ::: "memory")
#define CP_WAIT0()  asm volatile("cp.async.wait_group 0;" ::: "memory")

static __device__ __forceinline__ unsigned long long pack2(float lo, float hi) {
    unsigned long long r;
    asm("mov.b64 %0, {%1, %2};" : "=l"(r) : "f"(lo), "f"(hi));
    return r;
}
static __device__ __forceinline__ void fma2(unsigned long long &d,
                                            unsigned long long a, unsigned long long b) {
    asm("fma.rn.f32x2 %0, %1, %2, %0;" : "+l"(d) : "l"(a), "l"(b));
}
static __device__ __forceinline__ float2 unpack2(unsigned long long v) {
    float lo, hi;
    asm("mov.b64 {%0, %1}, %2;" : "=f"(lo), "=f"(hi) : "l"(v));
    return make_float2(lo, hi);
}
static __device__ __forceinline__ void split_bf16(float v, __nv_bfloat16& h, __nv_bfloat16& l) {
    h = __float2bfloat16_rn(v);
    l = __float2bfloat16_rn(v - __bfloat162float(h));
}
static __device__ __forceinline__ uint32_t packbf(__nv_bfloat16 a, __nv_bfloat16 b) {
    __nv_bfloat162 p = __halves2bfloat162(a, b);
    return *(uint32_t*)&p;
}

// ---------------------------------------------------------------------------
// Prologue: blocks [0,256): router split-K partials, 128 tok x 32 exp x K-half,
// 4x4 micro (round-2 geometry). Blocks [256, 8448): weight transpose + split.
// ---------------------------------------------------------------------------
#define RT 128
#define RDC 64
#define XPAD 68
#define NB_ROUTER 256

__global__ __launch_bounds__(256) void prologue_kernel(
    const float* __restrict__ x, const float* __restrict__ ctrl,
    const float* __restrict__ f1, const float* __restrict__ f2)
{
    __shared__ __align__(16) float sm[RT * XPAD + RDC * NE];
    int b   = blockIdx.x;
    int tid = threadIdx.x;

    if (b < NB_ROUTER) {
        float* xs = sm;                       // [128][XPAD]
        float (*cs)[NE] = (float(*)[NE])(sm + RT * XPAD);
        int tokbase = (b & 127) * RT;
        int khalf   = b >> 7;
        int kbase   = khalf * (DD / 2);

        int mt = (tid >> 3) << 2;   // token 0..124
        int et = (tid & 7) << 2;    // expert 0..28

        unsigned long long acc[4][2];
#pragma unroll
        for (int i = 0; i < 4; i++) { acc[i][0] = 0ULL; acc[i][1] = 0ULL; }

        for (int dc = kbase; dc < kbase + DD / 2; dc += RDC) {
            __syncthreads();
#pragma unroll
            for (int it = 0; it < 8; it++) {
                int t  = (tid >> 4) + (it << 4);
                int d4 = (tid & 15) << 2;
                *(float4*)&xs[t * XPAD + d4] =
                    *(const float4*)(x + (size_t)(tokbase + t) * DD + dc + d4);
            }
#pragma unroll
            for (int it = 0; it < 2; it++) {
                int q  = tid + (it << 8);
                int d  = q >> 3;
                int e4 = (q & 7) << 2;
                *(float4*)&cs[d][e4] = *(const float4*)(ctrl + (size_t)(dc + d) * NE + e4);
            }
            __syncthreads();
#pragma unroll 4
            for (int d = 0; d < RDC; d += 4) {
                float4 xr[4];
#pragma unroll
                for (int i = 0; i < 4; i++)
                    xr[i] = *(const float4*)&xs[(mt + i) * XPAD + d];
#pragma unroll
                for (int dd = 0; dd < 4; dd++) {
                    ulonglong2 cb = *(const ulonglong2*)&cs[d + dd][et];
                    float xv[4];
                    xv[0] = (dd == 0) ? xr[0].x : (dd == 1) ? xr[0].y : (dd == 2) ? xr[0].z : xr[0].w;
                    xv[1] = (dd == 0) ? xr[1].x : (dd == 1) ? xr[1].y : (dd == 2) ? xr[1].z : xr[1].w;
                    xv[2] = (dd == 0) ? xr[2].x : (dd == 1) ? xr[2].y : (dd == 2) ? xr[2].z : xr[2].w;
                    xv[3] = (dd == 0) ? xr[3].x : (dd == 1) ? xr[3].y : (dd == 2) ? xr[3].z : xr[3].w;
#pragma unroll
                    for (int i = 0; i < 4; i++) {
                        unsigned long long ad = pack2(xv[i], xv[i]);
                        fma2(acc[i][0], ad, cb.x);
                        fma2(acc[i][1], ad, cb.y);
                    }
                }
            }
        }

        float* Lp = g_Lp + (size_t)khalf * (NG * TG * NE);
#pragma unroll
        for (int i = 0; i < 4; i++) {
            float2 v0 = unpack2(acc[i][0]);
            float2 v1 = unpack2(acc[i][1]);
            *(float4*)&Lp[(size_t)(tokbase + mt + i) * NE + et] =
                make_float4(v0.x, v0.y, v1.x, v1.y);
        }
    } else {
        int idx = b - NB_ROUTER;                  // 0..8191
        float (*tile)[33] = (float(*)[33])sm;
        int z_  = idx >> 7;          // 0..63
        int bi  = idx & 31;
        int bj  = (idx >> 5) & 3;
        int tx  = tid & 31, ty = tid >> 5;
        if (z_ < 32) {
            int e = z_, nt = bj, kt = bi;
#pragma unroll
            for (int r = 0; r < 4; r++) {
                int k = kt * 32 + ty + r * 8;
                tile[ty + r * 8][tx] = f1[((size_t)k * NE + e) * NS + nt * 32 + tx];
            }
            __syncthreads();
#pragma unroll
            for (int r = 0; r < 4; r++) {
                int n = nt * 32 + ty + r * 8;
                int k = kt * 32 + tx;
                float v = tile[tx][ty + r * 8];
                __nv_bfloat16 h, l;
                split_bf16(v, h, l);
                size_t ix = ((size_t)e * NS + n) * DD + k;
                g_B1hi[ix] = h;
                g_B1lo[ix] = l;
            }
        } else {
            int e = z_ - 32, st = bj, dt = bi;
#pragma unroll
            for (int r = 0; r < 4; r++) {
                int s = st * 32 + ty + r * 8;
                tile[ty + r * 8][tx] = f2[((size_t)e * NS + s) * DD + dt * 32 + tx];
            }
            __syncthreads();
#pragma unroll
            for (int r = 0; r < 4; r++) {
                int d = dt * 32 + ty + r * 8;
                int s = st * 32 + tx;
                float v = tile[tx][ty + r * 8];
                __nv_bfloat16 h, l;
                split_bf16(v, h, l);
                size_t ix = ((size_t)e * DD + d) * NS + s;
                g_B2hi[ix] = h;
                g_B2lo[ix] = l;
            }
        }
    }
}

// Router finalize + reset counters (block 0).
__global__ __launch_bounds__(32) void router_fin_kernel()
{
    int g = blockIdx.x;
    int e = threadIdx.x;
    if (g == 0) {
        g_done[e] = 0u;
        if (e == 0) g_zero = 0u;
    }

    const float* p0 = g_Lp + (size_t)(g * TG) * NE + e;
    const float* p1 = p0 + (size_t)NG * TG * NE;
    const float step = 1e-6f / 31.0f;

    float L[TG];
    float m = -1e30f;
    int am = 0;
#pragma unroll
    for (int t = 0; t < TG; t++) {
        float v = p0[t * NE] + p1[t * NE] + (float)t * step;
        L[t] = v;
        if (v > m) { m = v; am = t; }
    }
    float s = 0.f;
#pragma unroll
    for (int t = 0; t < TG; t++) s += __expf(L[t] - m);
    g_w[g * NE + e]   = 1.0f / s;
    g_sel[g * NE + e] = am;
}

// ---------------------------------------------------------------------------
// Fused FF kernel:
//   blocks [0,256): ff1 role — zero-fill 256KB slice of out (signal g_zero),
//                   then D[64g,128s]=(w*x[sel])@B1^T, write g_I, signal g_done.
//   blocks [256,1280): ff2 role — wait g_zero==256 and g_done[e]==8, then
//                   D[128g,128d]=I@B2^T, scatter via red.v2.
// ---------------------------------------------------------------------------
#define RS 80
#define F1_AH 0
#define F1_AL 5120
#define F1_BH 10240
#define F1_BL 20480
#define F1_BUF 30720
#define F2_AH 0
#define F2_AL 10240
#define F2_BH 20480
#define F2_BL 30720
#define F2_BUF 40960
#define F2_WV  (2 * F2_BUF)
#define F2_TOK (F2_WV + 512)
#define FF_SMEM (F2_TOK + 512)
#define NB_FF1 256

__global__ __launch_bounds__(256) void fused_ff_kernel(
    const float* __restrict__ x, const float* __restrict__ f1b,
    float* __restrict__ out)
{
    extern __shared__ __align__(16) char smc[];
    uint32_t smu = smem_to_u32(smc);
    int tid  = threadIdx.x;
    int lane = tid & 31;
    int wid  = tid >> 5;
    int wm   = wid >> 2;
    int wn   = wid & 3;
    int b    = blockIdx.x;

    if (b < NB_FF1) {
        // ========================= FF1 role =========================
        // zero-fill this block's 16384-float4 slice of out, then signal
        {
            float4 z = make_float4(0.f, 0.f, 0.f, 0.f);
            int base = b * 16384 + tid;
#pragma unroll 8
            for (int j = 0; j < 64; j++)
                ((float4*)out)[base + j * 256] = z;
            __threadfence();
            __syncthreads();
            if (tid == 0) atomicAdd(&g_zero, 1u);
        }

        int e     = b >> 3;
        int gbase = (b & 7) * 64;

        int ar  = tid >> 2;
        int ac0 = (tid & 3) << 1;
        int gg  = gbase + ar;
        float wv = g_w[gg * NE + e];
        const float* arow = x + (size_t)(gg * TG + g_sel[gg * NE + e]) * DD;

        int br  = tid >> 1;
        int bh2 = tid & 1;
        const __nv_bfloat16* bhrow = g_B1hi + ((size_t)e * NS + br) * DD + bh2 * 16;
        const __nv_bfloat16* blrow = g_B1lo + ((size_t)e * NS + br) * DD + bh2 * 16;
        uint32_t bdst = smu + F1_BH + br * RS + bh2 * 32;

        float acc[2][4][4];
#pragma unroll
        for (int i = 0; i < 2; i++)
#pragma unroll
            for (int j = 0; j < 4; j++)
#pragma unroll
                for (int q = 0; q < 4; q++) acc[i][j][q] = 0.f;

        float4 pa[2];

#define FF1_FETCH_A(kt) do {                                                 \
        pa[0] = *(const float4*)(arow + (kt) + ac0 * 4);                     \
        pa[1] = *(const float4*)(arow + (kt) + ac0 * 4 + 4);                 \
    } while (0)

#define FF1_STORE_A(b_) do {                                                 \
        char* bb = smc + (b_) * F1_BUF;                                      \
        _Pragma("unroll")                                                    \
        for (int j = 0; j < 2; j++) {                                        \
            float4 v = pa[j];                                                \
            v.x *= wv; v.y *= wv; v.z *= wv; v.w *= wv;                      \
            __nv_bfloat16 h0,l0,h1,l1,h2,l2,h3,l3;                           \
            split_bf16(v.x,h0,l0); split_bf16(v.y,h1,l1);                    \
            split_bf16(v.z,h2,l2); split_bf16(v.w,h3,l3);                    \
            int off = ar * RS + (ac0 + j) * 8;                               \
            *(uint2*)(bb + F1_AH + off) = make_uint2(packbf(h0,h1), packbf(h2,h3)); \
            *(uint2*)(bb + F1_AL + off) = make_uint2(packbf(l0,l1), packbf(l2,l3)); \
        }                                                                    \
    } while (0)

#define FF1_CPASYNC_B(b_, kt) do {                                           \
        uint32_t d_ = bdst + (b_) * F1_BUF;                                  \
        CP_ASYNC16(d_,                      bhrow + (kt));                   \
        CP_ASYNC16(d_ + 16,                 bhrow + (kt) + 8);               \
        CP_ASYNC16(d_ + (F1_BL - F1_BH),      blrow + (kt));                 \
        CP_ASYNC16(d_ + (F1_BL - F1_BH) + 16, blrow + (kt) + 8);             \
    } while (0)

        FF1_FETCH_A(0);
        FF1_STORE_A(0);
        FF1_CPASYNC_B(0, 0);
        CP_COMMIT();

        int cur = 0;
        for (int it = 0; it < 32; it++) {
            bool more = (it + 1 < 32);
            CP_WAIT0();
            __syncthreads();
            if (more) {
                FF1_CPASYNC_B(cur ^ 1, (it + 1) * 32);
                CP_COMMIT();
                FF1_FETCH_A((it + 1) * 32);
            }
            uint32_t bufb = smu + cur * F1_BUF;
#pragma unroll
            for (int ksb = 0; ksb < 64; ksb += 32) {
                uint32_t bh_[4][2], bl_[4][2];
#pragma unroll
                for (int nb = 0; nb < 2; nb++) {
                    uint32_t baddr = bufb + F1_BH +
                        (uint32_t)((wn * 32 + nb * 16 + (lane & 7) + ((lane >> 4) & 1) * 8) * RS +
                                   ((lane >> 3) & 1) * 16 + ksb);
                    ldmat_x4(bh_[2*nb][0], bh_[2*nb][1], bh_[2*nb+1][0], bh_[2*nb+1][1], baddr);
                    ldmat_x4(bl_[2*nb][0], bl_[2*nb][1], bl_[2*nb+1][0], bl_[2*nb+1][1],
                             baddr + (F1_BL - F1_BH));
                }
#pragma unroll
                for (int mf = 0; mf < 2; mf++) {
                    uint32_t aaddr = bufb + F1_AH +
                        (uint32_t)((wm * 32 + mf * 16 + (lane & 15)) * RS +
                                   (lane >> 4) * 16 + ksb);
                    uint32_t ah0, ah1, ah2, ah3, al0, al1, al2, al3;
                    ldmat_x4(ah0, ah1, ah2, ah3, aaddr);
                    ldmat_x4(al0, al1, al2, al3, aaddr + (F1_AL - F1_AH));
#pragma unroll
                    for (int nf = 0; nf < 4; nf++)
                        mma16816(acc[mf][nf], ah0, ah1, ah2, ah3, bh_[nf][0], bh_[nf][1]);
#pragma unroll
                    for (int nf = 0; nf < 4; nf++)
                        mma16816(acc[mf][nf], ah0, ah1, ah2, ah3, bl_[nf][0], bl_[nf][1]);
#pragma unroll
                    for (int nf = 0; nf < 4; nf++)
                        mma16816(acc[mf][nf], al0, al1, al2, al3, bh_[nf][0], bh_[nf][1]);
                }
            }
            if (more) FF1_STORE_A(cur ^ 1);
            cur ^= 1;
        }

        const float* bias = f1b + e * NS;
#pragma unroll
        for (int mf = 0; mf < 2; mf++) {
#pragma unroll
            for (int nf = 0; nf < 4; nf++) {
                int c  = wn * 32 + nf * 8 + (lane & 3) * 2;
                float b0 = bias[c], b1 = bias[c + 1];
#pragma unroll
                for (int h = 0; h < 2; h++) {
                    int r = wm * 32 + mf * 16 + (lane >> 2) + h * 8;
                    float v0 = fmaxf(acc[mf][nf][2*h]     + b0, 0.f);
                    float v1 = fmaxf(acc[mf][nf][2*h + 1] + b1, 0.f);
                    __nv_bfloat16 h0, l0, h1, l1;
                    split_bf16(v0, h0, l0); split_bf16(v1, h1, l1);
                    size_t ob = ((size_t)e * NG + gbase + r) * NS + c;
                    *(uint32_t*)&g_Ihi[ob] = packbf(h0, h1);
                    *(uint32_t*)&g_Ilo[ob] = packbf(l0, l1);
                }
            }
        }
        __threadfence();
        __syncthreads();
        if (tid == 0) atomicAdd(&g_done[e], 1u);
        return;
    }

    // ========================= FF2 role =========================
    int id = b - NB_FF1;              // 0..1023, expert-major
    int e  = id >> 5;
    int gbase = ((id >> 3) & 3) * 128;
    int nbase = (id & 7) * 128;

    if (tid == 0) {
        while (*(volatile unsigned*)&g_zero < (unsigned)NB_FF1) __nanosleep(100);
        while (*(volatile unsigned*)&g_done[e] < 8u) __nanosleep(200);
    }
    __syncthreads();
    __threadfence();

    float* swv = (float*)(smc + F2_WV);
    int*   stok = (int*)(smc + F2_TOK);
    if (tid < 128) {
        int g = gbase + tid;
        swv[tid]  = g_w[g * NE + e];
        stok[tid] = g * TG + g_sel[g * NE + e];
    }

    int r_  = tid >> 1;
    int h2  = tid & 1;
    const __nv_bfloat16* ahrow = g_Ihi + ((size_t)e * NG + gbase + r_) * NS + h2 * 16;
    const __nv_bfloat16* alrow = g_Ilo + ((size_t)e * NG + gbase + r_) * NS + h2 * 16;
    const __nv_bfloat16* bhrow = g_B2hi + ((size_t)e * DD + nbase + r_) * NS + h2 * 16;
    const __nv_bfloat16* blrow = g_B2lo + ((size_t)e * DD + nbase + r_) * NS + h2 * 16;
    uint32_t adst = smu + F2_AH + r_ * RS + h2 * 32;
    uint32_t bdst = smu + F2_BH + r_ * RS + h2 * 32;

    float acc[4][4][4];
#pragma unroll
    for (int i = 0; i < 4; i++)
#pragma unroll
        for (int j = 0; j < 4; j++)
#pragma unroll
            for (int q = 0; q < 4; q++) acc[i][j][q] = 0.f;

#define FF2_CPASYNC(b_, kt) do {                                             \
        uint32_t ad_ = adst + (b_) * F2_BUF;                                 \
        uint32_t bd_ = bdst + (b_) * F2_BUF;                                 \
        CP_ASYNC16(ad_,                       ahrow + (kt));                 \
        CP_ASYNC16(ad_ + 16,                  ahrow + (kt) + 8);             \
        CP_ASYNC16(ad_ + (F2_AL - F2_AH),      alrow + (kt));                \
        CP_ASYNC16(ad_ + (F2_AL - F2_AH) + 16, alrow + (kt) + 8);            \
        CP_ASYNC16(bd_,                       bhrow + (kt));                 \
        CP_ASYNC16(bd_ + 16,                  bhrow + (kt) + 8);             \
        CP_ASYNC16(bd_ + (F2_BL - F2_BH),      blrow + (kt));                \
        CP_ASYNC16(bd_ + (F2_BL - F2_BH) + 16, blrow + (kt) + 8);            \
    } while (0)

    FF2_CPASYNC(0, 0);
    CP_COMMIT();

    int cur = 0;
    for (int it = 0; it < 4; it++) {
        bool more = (it + 1 < 4);
        CP_WAIT0();
        __syncthreads();
        if (more) {
            FF2_CPASYNC(cur ^ 1, (it + 1) * 32);
            CP_COMMIT();
        }
        uint32_t bufb = smu + cur * F2_BUF;
#pragma unroll
        for (int ksb = 0; ksb < 64; ksb += 32) {
            uint32_t bh_[4][2], bl_[4][2];
#pragma unroll
            for (int nb = 0; nb < 2; nb++) {
                uint32_t baddr = bufb + F2_BH +
                    (uint32_t)((wn * 32 + nb * 16 + (lane & 7) + ((lane >> 4) & 1) * 8) * RS +
                               ((lane >> 3) & 1) * 16 + ksb);
                ldmat_x4(bh_[2*nb][0], bh_[2*nb][1], bh_[2*nb+1][0], bh_[2*nb+1][1], baddr);
                ldmat_x4(bl_[2*nb][0], bl_[2*nb][1], bl_[2*nb+1][0], bl_[2*nb+1][1],
                         baddr + (F2_BL - F2_BH));
            }
#pragma unroll
            for (int mf = 0; mf < 4; mf++) {
                uint32_t aaddr = bufb + F2_AH +
                    (uint32_t)((wm * 64 + mf * 16 + (lane & 15)) * RS +
                               (lane >> 4) * 16 + ksb);
                uint32_t ah0, ah1, ah2, ah3, al0, al1, al2, al3;
                ldmat_x4(ah0, ah1, ah2, ah3, aaddr);
                ldmat_x4(al0, al1, al2, al3, aaddr + (F2_AL - F2_AH));
#pragma unroll
                for (int nf = 0; nf < 4; nf++)
                    mma16816(acc[mf][nf], ah0, ah1, ah2, ah3, bh_[nf][0], bh_[nf][1]);
#pragma unroll
                for (int nf = 0; nf < 4; nf++)
                    mma16816(acc[mf][nf], ah0, ah1, ah2, ah3, bl_[nf][0], bl_[nf][1]);
#pragma unroll
                for (int nf = 0; nf < 4; nf++)
                    mma16816(acc[mf][nf], al0, al1, al2, al3, bh_[nf][0], bh_[nf][1]);
            }
        }
        cur ^= 1;
    }

#pragma unroll
    for (int mf = 0; mf < 4; mf++) {
#pragma unroll
        for (int nf = 0; nf < 4; nf++) {
            int c = wn * 32 + nf * 8 + (lane & 3) * 2;
#pragma unroll
            for (int h = 0; h < 2; h++) {
                int r = wm * 64 + mf * 16 + (lane >> 2) + h * 8;
                float wv = swv[r];
                float* p = out + (size_t)stok[r] * DD + nbase + c;
                float v0 = wv * acc[mf][nf][2*h];
                float v1 = wv * acc[mf][nf][2*h + 1];
                asm volatile("red.global.add.v2.f32 [%0], {%1, %2};"
                             :: "l"(p), "f"(v0), "f"(v1) : "memory");
            }
        }
    }
}

// ---------------------------------------------------------------------------
extern "C" void kernel_launch(void* const* d_in, const int* in_sizes, int n_in,
                              void* d_out, int out_size) {
    const float* x    = (const float*)d_in[0];
    const float* ctrl = (const float*)d_in[1];
    const float* f1   = (const float*)d_in[2];
    const float* f2   = (const float*)d_in[3];
    const float* f1b  = (const float*)d_in[4];
    float* out = (float*)d_out;

    cudaFuncSetAttribute(fused_ff_kernel, cudaFuncAttributeMaxDynamicSharedMemorySize, FF_SMEM);

    prologue_kernel<<<NB_ROUTER + 8192, 256>>>(x, ctrl, f1, f2);
    router_fin_kernel<<<NG, 32>>>();
    fused_ff_kernel<<<NB_FF1 + 1024, 256, FF_SMEM>>>(x, f1b, out);
}

// round 17
// speedup vs baseline: 1.1127x; 1.0313x over previous
#include <cuda_runtime.h>
#include <cuda_bf16.h>
#include <cstdint>

#define NG 512   // total groups
#define TG 32    // tokens per group
#define DD 1024  // model dim
#define NE 32    // experts
#define NS 128   // expert hidden size

__device__ float g_w[NG * NE];
__device__ int   g_sel[NG * NE];
__device__ float g_Lp[4 * NG * TG * NE];   // split-K(4) partial logits (8 MB)
__device__ unsigned g_done[NE];            // ff1 per-expert completion counters
__device__ unsigned g_zero;                // out zero-fill completion counter
__device__ __nv_bfloat16 g_B1hi[(size_t)NE * NS * DD];
__device__ __nv_bfloat16 g_B1lo[(size_t)NE * NS * DD];
__device__ __nv_bfloat16 g_B2hi[(size_t)NE * DD * NS];
__device__ __nv_bfloat16 g_B2lo[(size_t)NE * DD * NS];
__device__ __nv_bfloat16 g_Ihi[(size_t)NE * NG * NS];
__device__ __nv_bfloat16 g_Ilo[(size_t)NE * NG * NS];

// ============================ helpers ============================
static __device__ __forceinline__ uint32_t smem_to_u32(const void* p) {
    uint32_t a;
    asm("{ .reg .u64 t; cvta.to.shared.u64 t, %1; cvt.u32.u64 %0, t; }"
        : "=r"(a) : "l"(p));
    return a;
}
static __device__ __forceinline__ void ldmat_x4(
    uint32_t& r0, uint32_t& r1, uint32_t& r2, uint32_t& r3, uint32_t addr)
{
    asm volatile("ldmatrix.sync.aligned.m8n8.x4.shared.b16 {%0,%1,%2,%3}, [%4];"
                 : "=r"(r0), "=r"(r1), "=r"(r2), "=r"(r3) : "r"(addr));
}
static __device__ __forceinline__ void mma16816(
    float* d, uint32_t a0, uint32_t a1, uint32_t a2, uint32_t a3,
    uint32_t b0, uint32_t b1)
{
    asm volatile("mma.sync.aligned.m16n8k16.row.col.f32.bf16.bf16.f32 "
                 "{%0,%1,%2,%3}, {%4,%5,%6,%7}, {%8,%9}, {%0,%1,%2,%3};"
                 : "+f"(d[0]), "+f"(d[1]), "+f"(d[2]), "+f"(d[3])
                 : "r"(a0), "r"(a1), "r"(a2), "r"(a3), "r"(b0), "r"(b1));
}
#define CP_ASYNC16(sm, gp) \
    asm volatile("cp.async.cg.shared.global [%0], [%1], 16;" :: "r"(sm), "l"(gp))
#define CP_COMMIT() asm volatile("cp.async.commit_group;" ::: "memory")
#define CP_WAIT0()  asm volatile("cp.async.wait_group 0;" ::: "memory")

static __device__ __forceinline__ unsigned long long pack2(float lo, float hi) {
    unsigned long long r;
    asm("mov.b64 %0, {%1, %2};" : "=l"(r) : "f"(lo), "f"(hi));
    return r;
}
static __device__ __forceinline__ void fma2(unsigned long long &d,
                                            unsigned long long a, unsigned long long b) {
    asm("fma.rn.f32x2 %0, %1, %2, %0;" : "+l"(d) : "l"(a), "l"(b));
}
static __device__ __forceinline__ float2 unpack2(unsigned long long v) {
    float lo, hi;
    asm("mov.b64 {%0, %1}, %2;" : "=f"(lo), "=f"(hi) : "l"(v));
    return make_float2(lo, hi);
}
static __device__ __forceinline__ void split_bf16(float v, __nv_bfloat16& h, __nv_bfloat16& l) {
    h = __float2bfloat16_rn(v);
    l = __float2bfloat16_rn(v - __bfloat162float(h));
}
static __device__ __forceinline__ uint32_t packbf(__nv_bfloat16 a, __nv_bfloat16 b) {
    __nv_bfloat162 p = __halves2bfloat162(a, b);
    return *(uint32_t*)&p;
}

// ---------------------------------------------------------------------------
// Prologue:
//   blocks [0,512): router split-K(4) partials, 128 tok x 32 exp x K-quarter,
//                   4x4 micro.
//   blocks [512, 2560): weight transpose + bf16 split, 4 tiles per block with
//                   register prefetch (idx<1024: f1 tiles, else f2 tiles).
// ---------------------------------------------------------------------------
#define RT 128
#define RDC 64
#define XPAD 68
#define NB_ROUTER 512

__global__ __launch_bounds__(256) void prologue_kernel(
    const float* __restrict__ x, const float* __restrict__ ctrl,
    const float* __restrict__ f1, const float* __restrict__ f2)
{
    __shared__ __align__(16) float sm[RT * XPAD + RDC * NE];
    int b   = blockIdx.x;
    int tid = threadIdx.x;

    if (b < NB_ROUTER) {
        float* xs = sm;                       // [128][XPAD]
        float (*cs)[NE] = (float(*)[NE])(sm + RT * XPAD);
        int tokbase = (b & 127) * RT;
        int khalf   = b >> 7;                 // 0..3
        int kbase   = khalf * (DD / 4);

        int mt = (tid >> 3) << 2;   // token 0..124
        int et = (tid & 7) << 2;    // expert 0..28

        unsigned long long acc[4][2];
#pragma unroll
        for (int i = 0; i < 4; i++) { acc[i][0] = 0ULL; acc[i][1] = 0ULL; }

        for (int dc = kbase; dc < kbase + DD / 4; dc += RDC) {
            __syncthreads();
#pragma unroll
            for (int it = 0; it < 8; it++) {
                int t  = (tid >> 4) + (it << 4);
                int d4 = (tid & 15) << 2;
                *(float4*)&xs[t * XPAD + d4] =
                    *(const float4*)(x + (size_t)(tokbase + t) * DD + dc + d4);
            }
#pragma unroll
            for (int it = 0; it < 2; it++) {
                int q  = tid + (it << 8);
                int d  = q >> 3;
                int e4 = (q & 7) << 2;
                *(float4*)&cs[d][e4] = *(const float4*)(ctrl + (size_t)(dc + d) * NE + e4);
            }
            __syncthreads();
#pragma unroll 4
            for (int d = 0; d < RDC; d += 4) {
                float4 xr[4];
#pragma unroll
                for (int i = 0; i < 4; i++)
                    xr[i] = *(const float4*)&xs[(mt + i) * XPAD + d];
#pragma unroll
                for (int dd = 0; dd < 4; dd++) {
                    ulonglong2 cb = *(const ulonglong2*)&cs[d + dd][et];
                    float xv[4];
                    xv[0] = (dd == 0) ? xr[0].x : (dd == 1) ? xr[0].y : (dd == 2) ? xr[0].z : xr[0].w;
                    xv[1] = (dd == 0) ? xr[1].x : (dd == 1) ? xr[1].y : (dd == 2) ? xr[1].z : xr[1].w;
                    xv[2] = (dd == 0) ? xr[2].x : (dd == 1) ? xr[2].y : (dd == 2) ? xr[2].z : xr[2].w;
                    xv[3] = (dd == 0) ? xr[3].x : (dd == 1) ? xr[3].y : (dd == 2) ? xr[3].z : xr[3].w;
#pragma unroll
                    for (int i = 0; i < 4; i++) {
                        unsigned long long ad = pack2(xv[i], xv[i]);
                        fma2(acc[i][0], ad, cb.x);
                        fma2(acc[i][1], ad, cb.y);
                    }
                }
            }
        }

        float* Lp = g_Lp + (size_t)khalf * (NG * TG * NE);
#pragma unroll
        for (int i = 0; i < 4; i++) {
            float2 v0 = unpack2(acc[i][0]);
            float2 v1 = unpack2(acc[i][1]);
            *(float4*)&Lp[(size_t)(tokbase + mt + i) * NE + et] =
                make_float4(v0.x, v0.y, v1.x, v1.y);
        }
    } else {
        // ----- 4 transpose tiles per block, register-prefetched -----
        int idx   = b - NB_ROUTER;            // 0..2047
        bool isf1 = (idx < 1024);
        int base_t = (isf1 ? idx : idx - 1024) * 4;
        const float* src = isf1 ? f1 : f2;
        int tx = tid & 31, ty = tid >> 5;     // 32 x 8

        float rg[2][4];
        // load tile base_t into rg[0]
        {
            int tl = base_t;
            int e = tl >> 7, bi = tl & 31, bj = (tl >> 5) & 3;
#pragma unroll
            for (int r = 0; r < 4; r++) {
                int rr = bj * 32 + ty + r * 8;   // n (f1) / s (f2) ... see below
                if (isf1) {
                    int k = bi * 32 + ty + r * 8;
                    rg[0][r] = src[((size_t)k * NE + e) * NS + bj * 32 + tx];
                } else {
                    int s = bj * 32 + ty + r * 8;
                    rg[0][r] = src[((size_t)e * NS + s) * DD + bi * 32 + tx];
                }
                (void)rr;
            }
        }

        for (int t = 0; t < 4; t++) {
            float (*tb)[33] = (float(*)[33])(sm + (t & 1) * (32 * 33));
            int tl = base_t + t;
            int e = tl >> 7, bi = tl & 31, bj = (tl >> 5) & 3;
            // stage current regs into smem
#pragma unroll
            for (int r = 0; r < 4; r++)
                tb[ty + r * 8][tx] = rg[t & 1][r];
            // prefetch next tile
            if (t < 3) {
                int tn = tl + 1;
                int e2 = tn >> 7, bi2 = tn & 31, bj2 = (tn >> 5) & 3;
#pragma unroll
                for (int r = 0; r < 4; r++) {
                    if (isf1) {
                        int k = bi2 * 32 + ty + r * 8;
                        rg[(t + 1) & 1][r] = src[((size_t)k * NE + e2) * NS + bj2 * 32 + tx];
                    } else {
                        int s = bj2 * 32 + ty + r * 8;
                        rg[(t + 1) & 1][r] = src[((size_t)e2 * NS + s) * DD + bi2 * 32 + tx];
                    }
                }
            }
            __syncthreads();
            // transposed read + split + store
#pragma unroll
            for (int r = 0; r < 4; r++) {
                float v = tb[tx][ty + r * 8];
                __nv_bfloat16 h, l;
                split_bf16(v, h, l);
                if (isf1) {
                    int n = bj * 32 + ty + r * 8;
                    int k = bi * 32 + tx;
                    size_t ix = ((size_t)e * NS + n) * DD + k;
                    g_B1hi[ix] = h;
                    g_B1lo[ix] = l;
                } else {
                    int d = bi * 32 + ty + r * 8;
                    int s = bj * 32 + tx;
                    size_t ix = ((size_t)e * DD + d) * NS + s;
                    g_B2hi[ix] = h;
                    g_B2lo[ix] = l;
                }
            }
            __syncthreads();
        }
    }
}

// Router finalize (sum 4 partials) + reset counters (block 0).
__global__ __launch_bounds__(32) void router_fin_kernel()
{
    int g = blockIdx.x;
    int e = threadIdx.x;
    if (g == 0) {
        g_done[e] = 0u;
        if (e == 0) g_zero = 0u;
    }

    const size_t stride = (size_t)NG * TG * NE;
    const float* p0 = g_Lp + (size_t)(g * TG) * NE + e;
    const float step = 1e-6f / 31.0f;

    float L[TG];
    float m = -1e30f;
    int am = 0;
#pragma unroll
    for (int t = 0; t < TG; t++) {
        float v = p0[t * NE] + p0[t * NE + stride]
                + p0[t * NE + 2 * stride] + p0[t * NE + 3 * stride]
                + (float)t * step;
        L[t] = v;
        if (v > m) { m = v; am = t; }
    }
    float s = 0.f;
#pragma unroll
    for (int t = 0; t < TG; t++) s += __expf(L[t] - m);
    g_w[g * NE + e]   = 1.0f / s;
    g_sel[g * NE + e] = am;
}

// ---------------------------------------------------------------------------
// Fused FF kernel (unchanged from round 16):
//   blocks [0,256): ff1 role — zero-fill slice of out (signal g_zero),
//                   then D[64g,128s]=(w*x[sel])@B1^T, write g_I, signal g_done.
//   blocks [256,1280): ff2 role — wait g_zero==256 and g_done[e]==8, then
//                   D[128g,128d]=I@B2^T, scatter via red.v2.
// ---------------------------------------------------------------------------
#define RS 80
#define F1_AH 0
#define F1_AL 5120
#define F1_BH 10240
#define F1_BL 20480
#define F1_BUF 30720
#define F2_AH 0
#define F2_AL 10240
#define F2_BH 20480
#define F2_BL 30720
#define F2_BUF 40960
#define F2_WV  (2 * F2_BUF)
#define F2_TOK (F2_WV + 512)
#define FF_SMEM (F2_TOK + 512)
#define NB_FF1 256

__global__ __launch_bounds__(256) void fused_ff_kernel(
    const float* __restrict__ x, const float* __restrict__ f1b,
    float* __restrict__ out)
{
    extern __shared__ __align__(16) char smc[];
    uint32_t smu = smem_to_u32(smc);
    int tid  = threadIdx.x;
    int lane = tid & 31;
    int wid  = tid >> 5;
    int wm   = wid >> 2;
    int wn   = wid & 3;
    int b    = blockIdx.x;

    if (b < NB_FF1) {
        // ========================= FF1 role =========================
        {
            float4 z = make_float4(0.f, 0.f, 0.f, 0.f);
            int base = b * 16384 + tid;
#pragma unroll 8
            for (int j = 0; j < 64; j++)
                ((float4*)out)[base + j * 256] = z;
            __threadfence();
            __syncthreads();
            if (tid == 0) atomicAdd(&g_zero, 1u);
        }

        int e     = b >> 3;
        int gbase = (b & 7) * 64;

        int ar  = tid >> 2;
        int ac0 = (tid & 3) << 1;
        int gg  = gbase + ar;
        float wv = g_w[gg * NE + e];
        const float* arow = x + (size_t)(gg * TG + g_sel[gg * NE + e]) * DD;

        int br  = tid >> 1;
        int bh2 = tid & 1;
        const __nv_bfloat16* bhrow = g_B1hi + ((size_t)e * NS + br) * DD + bh2 * 16;
        const __nv_bfloat16* blrow = g_B1lo + ((size_t)e * NS + br) * DD + bh2 * 16;
        uint32_t bdst = smu + F1_BH + br * RS + bh2 * 32;

        float acc[2][4][4];
#pragma unroll
        for (int i = 0; i < 2; i++)
#pragma unroll
            for (int j = 0; j < 4; j++)
#pragma unroll
                for (int q = 0; q < 4; q++) acc[i][j][q] = 0.f;

        float4 pa[2];

#define FF1_FETCH_A(kt) do {                                                 \
        pa[0] = *(const float4*)(arow + (kt) + ac0 * 4);                     \
        pa[1] = *(const float4*)(arow + (kt) + ac0 * 4 + 4);                 \
    } while (0)

#define FF1_STORE_A(b_) do {                                                 \
        char* bb = smc + (b_) * F1_BUF;                                      \
        _Pragma("unroll")                                                    \
        for (int j = 0; j < 2; j++) {                                        \
            float4 v = pa[j];                                                \
            v.x *= wv; v.y *= wv; v.z *= wv; v.w *= wv;                      \
            __nv_bfloat16 h0,l0,h1,l1,h2,l2,h3,l3;                           \
            split_bf16(v.x,h0,l0); split_bf16(v.y,h1,l1);                    \
            split_bf16(v.z,h2,l2); split_bf16(v.w,h3,l3);                    \
            int off = ar * RS + (ac0 + j) * 8;                               \
            *(uint2*)(bb + F1_AH + off) = make_uint2(packbf(h0,h1), packbf(h2,h3)); \
            *(uint2*)(bb + F1_AL + off) = make_uint2(packbf(l0,l1), packbf(l2,l3)); \
        }                                                                    \
    } while (0)

#define FF1_CPASYNC_B(b_, kt) do {                                           \
        uint32_t d_ = bdst + (b_) * F1_BUF;                                  \
        CP_ASYNC16(d_,                      bhrow + (kt));                   \
        CP_ASYNC16(d_ + 16,                 bhrow + (kt) + 8);               \
        CP_ASYNC16(d_ + (F1_BL - F1_BH),      blrow + (kt));                 \
        CP_ASYNC16(d_ + (F1_BL - F1_BH) + 16, blrow + (kt) + 8);             \
    } while (0)

        FF1_FETCH_A(0);
        FF1_STORE_A(0);
        FF1_CPASYNC_B(0, 0);
        CP_COMMIT();

        int cur = 0;
        for (int it = 0; it < 32; it++) {
            bool more = (it + 1 < 32);
            CP_WAIT0();
            __syncthreads();
            if (more) {
                FF1_CPASYNC_B(cur ^ 1, (it + 1) * 32);
                CP_COMMIT();
                FF1_FETCH_A((it + 1) * 32);
            }
            uint32_t bufb = smu + cur * F1_BUF;
#pragma unroll
            for (int ksb = 0; ksb < 64; ksb += 32) {
                uint32_t bh_[4][2], bl_[4][2];
#pragma unroll
                for (int nb = 0; nb < 2; nb++) {
                    uint32_t baddr = bufb + F1_BH +
                        (uint32_t)((wn * 32 + nb * 16 + (lane & 7) + ((lane >> 4) & 1) * 8) * RS +
                                   ((lane >> 3) & 1) * 16 + ksb);
                    ldmat_x4(bh_[2*nb][0], bh_[2*nb][1], bh_[2*nb+1][0], bh_[2*nb+1][1], baddr);
                    ldmat_x4(bl_[2*nb][0], bl_[2*nb][1], bl_[2*nb+1][0], bl_[2*nb+1][1],
                             baddr + (F1_BL - F1_BH));
                }
#pragma unroll
                for (int mf = 0; mf < 2; mf++) {
                    uint32_t aaddr = bufb + F1_AH +
                        (uint32_t)((wm * 32 + mf * 16 + (lane & 15)) * RS +
                                   (lane >> 4) * 16 + ksb);
                    uint32_t ah0, ah1, ah2, ah3, al0, al1, al2, al3;
                    ldmat_x4(ah0, ah1, ah2, ah3, aaddr);
                    ldmat_x4(al0, al1, al2, al3, aaddr + (F1_AL - F1_AH));
#pragma unroll
                    for (int nf = 0; nf < 4; nf++)
                        mma16816(acc[mf][nf], ah0, ah1, ah2, ah3, bh_[nf][0], bh_[nf][1]);
#pragma unroll
                    for (int nf = 0; nf < 4; nf++)
                        mma16816(acc[mf][nf], ah0, ah1, ah2, ah3, bl_[nf][0], bl_[nf][1]);
#pragma unroll
                    for (int nf = 0; nf < 4; nf++)
                        mma16816(acc[mf][nf], al0, al1, al2, al3, bh_[nf][0], bh_[nf][1]);
                }
            }
            if (more) FF1_STORE_A(cur ^ 1);
            cur ^= 1;
        }

        const float* bias = f1b + e * NS;
#pragma unroll
        for (int mf = 0; mf < 2; mf++) {
#pragma unroll
            for (int nf = 0; nf < 4; nf++) {
                int c  = wn * 32 + nf * 8 + (lane & 3) * 2;
                float b0 = bias[c], b1 = bias[c + 1];
#pragma unroll
                for (int h = 0; h < 2; h++) {
                    int r = wm * 32 + mf * 16 + (lane >> 2) + h * 8;
                    float v0 = fmaxf(acc[mf][nf][2*h]     + b0, 0.f);
                    float v1 = fmaxf(acc[mf][nf][2*h + 1] + b1, 0.f);
                    __nv_bfloat16 h0, l0, h1, l1;
                    split_bf16(v0, h0, l0); split_bf16(v1, h1, l1);
                    size_t ob = ((size_t)e * NG + gbase + r) * NS + c;
                    *(uint32_t*)&g_Ihi[ob] = packbf(h0, h1);
                    *(uint32_t*)&g_Ilo[ob] = packbf(l0, l1);
                }
            }
        }
        __threadfence();
        __syncthreads();
        if (tid == 0) atomicAdd(&g_done[e], 1u);
        return;
    }

    // ========================= FF2 role =========================
    int id = b - NB_FF1;              // 0..1023, expert-major
    int e  = id >> 5;
    int gbase = ((id >> 3) & 3) * 128;
    int nbase = (id & 7) * 128;

    if (tid == 0) {
        while (*(volatile unsigned*)&g_zero < (unsigned)NB_FF1) __nanosleep(100);
        while (*(volatile unsigned*)&g_done[e] < 8u) __nanosleep(200);
    }
    __syncthreads();
    __threadfence();

    float* swv = (float*)(smc + F2_WV);
    int*   stok = (int*)(smc + F2_TOK);
    if (tid < 128) {
        int g = gbase + tid;
        swv[tid]  = g_w[g * NE + e];
        stok[tid] = g * TG + g_sel[g * NE + e];
    }

    int r_  = tid >> 1;
    int h2  = tid & 1;
    const __nv_bfloat16* ahrow = g_Ihi + ((size_t)e * NG + gbase + r_) * NS + h2 * 16;
    const __nv_bfloat16* alrow = g_Ilo + ((size_t)e * NG + gbase + r_) * NS + h2 * 16;
    const __nv_bfloat16* bhrow = g_B2hi + ((size_t)e * DD + nbase + r_) * NS + h2 * 16;
    const __nv_bfloat16* blrow = g_B2lo + ((size_t)e * DD + nbase + r_) * NS + h2 * 16;
    uint32_t adst = smu + F2_AH + r_ * RS + h2 * 32;
    uint32_t bdst = smu + F2_BH + r_ * RS + h2 * 32;

    float acc[4][4][4];
#pragma unroll
    for (int i = 0; i < 4; i++)
#pragma unroll
        for (int j = 0; j < 4; j++)
#pragma unroll
            for (int q = 0; q < 4; q++) acc[i][j][q] = 0.f;

#define FF2_CPASYNC(b_, kt) do {                                             \
        uint32_t ad_ = adst + (b_) * F2_BUF;                                 \
        uint32_t bd_ = bdst + (b_) * F2_BUF;                                 \
        CP_ASYNC16(ad_,                       ahrow + (kt));                 \
        CP_ASYNC16(ad_ + 16,                  ahrow + (kt) + 8);             \
        CP_ASYNC16(ad_ + (F2_AL - F2_AH),      alrow + (kt));                \
        CP_ASYNC16(ad_ + (F2_AL - F2_AH) + 16, alrow + (kt) + 8);            \
        CP_ASYNC16(bd_,                       bhrow + (kt));                 \
        CP_ASYNC16(bd_ + 16,                  bhrow + (kt) + 8);             \
        CP_ASYNC16(bd_ + (F2_BL - F2_BH),      blrow + (kt));                \
        CP_ASYNC16(bd_ + (F2_BL - F2_BH) + 16, blrow + (kt) + 8);            \
    } while (0)

    FF2_CPASYNC(0, 0);
    CP_COMMIT();

    int cur = 0;
    for (int it = 0; it < 4; it++) {
        bool more = (it + 1 < 4);
        CP_WAIT0();
        __syncthreads();
        if (more) {
            FF2_CPASYNC(cur ^ 1, (it + 1) * 32);
            CP_COMMIT();
        }
        uint32_t bufb = smu + cur * F2_BUF;
#pragma unroll
        for (int ksb = 0; ksb < 64; ksb += 32) {
            uint32_t bh_[4][2], bl_[4][2];
#pragma unroll
            for (int nb = 0; nb < 2; nb++) {
                uint32_t baddr = bufb + F2_BH +
                    (uint32_t)((wn * 32 + nb * 16 + (lane & 7) + ((lane >> 4) & 1) * 8) * RS +
                               ((lane >> 3) & 1) * 16 + ksb);
                ldmat_x4(bh_[2*nb][0], bh_[2*nb][1], bh_[2*nb+1][0], bh_[2*nb+1][1], baddr);
                ldmat_x4(bl_[2*nb][0], bl_[2*nb][1], bl_[2*nb+1][0], bl_[2*nb+1][1],
                         baddr + (F2_BL - F2_BH));
            }
#pragma unroll
            for (int mf = 0; mf < 4; mf++) {
                uint32_t aaddr = bufb + F2_AH +
                    (uint32_t)((wm * 64 + mf * 16 + (lane & 15)) * RS +
                               (lane >> 4) * 16 + ksb);
                uint32_t ah0, ah1, ah2, ah3, al0, al1, al2, al3;
                ldmat_x4(ah0, ah1, ah2, ah3, aaddr);
                ldmat_x4(al0, al1, al2, al3, aaddr + (F2_AL - F2_AH));
#pragma unroll
                for (int nf = 0; nf < 4; nf++)
                    mma16816(acc[mf][nf], ah0, ah1, ah2, ah3, bh_[nf][0], bh_[nf][1]);
#pragma unroll
                for (int nf = 0; nf < 4; nf++)
                    mma16816(acc[mf][nf], ah0, ah1, ah2, ah3, bl_[nf][0], bl_[nf][1]);
#pragma unroll
                for (int nf = 0; nf < 4; nf++)
                    mma16816(acc[mf][nf], al0, al1, al2, al3, bh_[nf][0], bh_[nf][1]);
            }
        }
        cur ^= 1;
    }

#pragma unroll
    for (int mf = 0; mf < 4; mf++) {
#pragma unroll
        for (int nf = 0; nf < 4; nf++) {
            int c = wn * 32 + nf * 8 + (lane & 3) * 2;
#pragma unroll
            for (int h = 0; h < 2; h++) {
                int r = wm * 64 + mf * 16 + (lane >> 2) + h * 8;
                float wv = swv[r];
                float* p = out + (size_t)stok[r] * DD + nbase + c;
                float v0 = wv * acc[mf][nf][2*h];
                float v1 = wv * acc[mf][nf][2*h + 1];
                asm volatile("red.global.add.v2.f32 [%0], {%1, %2};"
                             :: "l"(p), "f"(v0), "f"(v1) : "memory");
            }
        }
    }
}

// ---------------------------------------------------------------------------
extern "C" void kernel_launch(void* const* d_in, const int* in_sizes, int n_in,
                              void* d_out, int out_size) {
    const float* x    = (const float*)d_in[0];
    const float* ctrl = (const float*)d_in[1];
    const float* f1   = (const float*)d_in[2];
    const float* f2   = (const float*)d_in[3];
    const float* f1b  = (const float*)d_in[4];
    float* out = (float*)d_out;

    cudaFuncSetAttribute(fused_ff_kernel, cudaFuncAttributeMaxDynamicSharedMemorySize, FF_SMEM);

    prologue_kernel<<<NB_ROUTER + 2048, 256>>>(x, ctrl, f1, f2);
    router_fin_kernel<<<NG, 32>>>();
    fused_ff_kernel<<<NB_FF1 + 1024, 256, FF_SMEM>>>(x, f1b, out);
}